// round 5
// baseline (speedup 1.0000x reference)
#include <cuda_runtime.h>
#include <cstdint>
#include <math.h>

#define S_LEN 4096
#define BATCH 2
#define DM    768
#define DFF   3072
#define NH    12
#define DK    64
#define NTOK  (BATCH * S_LEN)

// ---------------- scratch (device globals: no allocation allowed) ----------
__device__ float g_h  [NTOK * DM];
__device__ float g_q  [NTOK * DM];
__device__ float g_k  [NTOK * DM];
__device__ float g_v  [NTOK * DM];
__device__ float g_ctx[NTOK * DM];
__device__ float g_x2 [NTOK * DM];
__device__ float g_ff [NTOK * DFF];

// ---------------- helpers --------------------------------------------------
__device__ __forceinline__ uint32_t f2tf32(float f) {
    uint32_t r; asm("cvt.rna.tf32.f32 %0, %1;" : "=r"(r) : "f"(f)); return r;
}

__device__ __forceinline__ void mma_tf32(float c[4], const uint4& a, const uint2& b) {
    asm volatile(
        "mma.sync.aligned.m16n8k8.row.col.f32.tf32.tf32.f32 "
        "{%0,%1,%2,%3}, {%4,%5,%6,%7}, {%8,%9}, {%0,%1,%2,%3};"
        : "+f"(c[0]), "+f"(c[1]), "+f"(c[2]), "+f"(c[3])
        : "r"(a.x), "r"(a.y), "r"(a.z), "r"(a.w), "r"(b.x), "r"(b.y));
}

// ---------------- layernorm-ish (scalar alpha/beta, ddof=1 std) -----------
__global__ void norm_kernel(const float* __restrict__ x, float* __restrict__ out,
                            const float* __restrict__ alpha, const float* __restrict__ beta) {
    const int row = blockIdx.x;
    const float* xr = x + (size_t)row * DM;
    float* orow = out + (size_t)row * DM;

    float v0 = xr[threadIdx.x];
    float v1 = xr[threadIdx.x + 256];
    float v2 = xr[threadIdx.x + 512];
    float s  = v0 + v1 + v2;
    float sq = v0 * v0 + v1 * v1 + v2 * v2;

    __shared__ float red0[8], red1[8];
    __shared__ float s_mean, s_scale, s_beta;
    #pragma unroll
    for (int o = 16; o > 0; o >>= 1) {
        s  += __shfl_xor_sync(0xffffffffu, s,  o);
        sq += __shfl_xor_sync(0xffffffffu, sq, o);
    }
    const int warp = threadIdx.x >> 5, lane = threadIdx.x & 31;
    if (lane == 0) { red0[warp] = s; red1[warp] = sq; }
    __syncthreads();
    if (threadIdx.x == 0) {
        float S = 0.f, SQ = 0.f;
        #pragma unroll
        for (int i = 0; i < 8; i++) { S += red0[i]; SQ += red1[i]; }
        const float mean = S / (float)DM;
        float var = (SQ - (float)DM * mean * mean) / (float)(DM - 1);
        var = fmaxf(var, 0.f);
        s_mean  = mean;
        s_scale = alpha[0] / (sqrtf(var) + 1e-6f);
        s_beta  = beta[0];
    }
    __syncthreads();
    const float mean = s_mean, scale = s_scale, bb = s_beta;
    orow[threadIdx.x]       = (v0 - mean) * scale + bb;
    orow[threadIdx.x + 256] = (v1 - mean) * scale + bb;
    orow[threadIdx.x + 512] = (v2 - mean) * scale + bb;
}

// =================== tf32 mma.sync GEMM, double-buffered ===================
// C[M,N] = A[M,K] @ W[N,K]^T (+bias) (+res) (+relu)
// CTA tile 128x128, K-tile 32, 8 warps (64m x 32n each).
// One __syncthreads per K-tile: sts(i+1) targets the buffer whose readers
// finished at the end of iteration i-1 (protected by that iteration's sync).
#define GEMM_SMEM_BYTES (2 * 8192 * 4)

template <bool RELU, bool HAS_RES>
__global__ void __launch_bounds__(256)
gemm_mma(const float* __restrict__ A, const float* __restrict__ W,
         const float* __restrict__ bias, const float* __restrict__ res,
         float* __restrict__ C, int M, int N, int K) {
    extern __shared__ uint32_t gs[];   // [2][As 4096 | Bs 4096]

    const int t    = threadIdx.x;
    const int lane = t & 31;
    const int wid  = t >> 5;
    const int wy   = wid >> 2;
    const int wx   = wid & 3;
    const int bm   = blockIdx.y * 128;
    const int bn   = blockIdx.x * 128;

    const float* Ab = A + (size_t)bm * K;
    const float* Wb = W + (size_t)bn * K;

    int rowp[4], gp[4];
    #pragma unroll
    for (int p = 0; p < 4; p++) {
        const int f = t + p * 256;
        rowp[p] = f >> 3;
        gp[p]   = f & 7;
    }

    float acc[4][4][4];
    #pragma unroll
    for (int i = 0; i < 4; i++)
        #pragma unroll
        for (int j = 0; j < 4; j++)
            #pragma unroll
            for (int r = 0; r < 4; r++) acc[i][j][r] = 0.f;

    float4 pa[4], pb[4];

    auto gload = [&](int k0) {
        #pragma unroll
        for (int p = 0; p < 4; p++) {
            pa[p] = *(const float4*)(Ab + (size_t)rowp[p] * K + k0 + gp[p] * 4);
            pb[p] = *(const float4*)(Wb + (size_t)rowp[p] * K + k0 + gp[p] * 4);
        }
    };

    auto sts = [&](int buf) {
        uint32_t* As = gs + buf * 8192;
        uint32_t* Bs = As + 4096;
        #pragma unroll
        for (int p = 0; p < 4; p++) {
            const int row = rowp[p], g = gp[p];
            const int k8 = g >> 1, khi = g & 1;
            {
                const int mt = row >> 4, rr = row & 15;
                const int reg = (rr >> 3) + 2 * khi;
                const int base = ((k8 * 8 + mt) * 32 + (rr & 7) * 4) * 4 + reg;
                As[base +  0] = f2tf32(pa[p].x);
                As[base +  4] = f2tf32(pa[p].y);
                As[base +  8] = f2tf32(pa[p].z);
                As[base + 12] = f2tf32(pa[p].w);
            }
            {
                const int nt = row >> 3, nr = row & 7;
                const int base = ((k8 * 16 + nt) * 32 + nr * 4) * 2 + khi;
                Bs[base + 0] = f2tf32(pb[p].x);
                Bs[base + 2] = f2tf32(pb[p].y);
                Bs[base + 4] = f2tf32(pb[p].z);
                Bs[base + 6] = f2tf32(pb[p].w);
            }
        }
    };

    auto compute = [&](int buf) {
        const uint32_t* As = gs + buf * 8192;
        const uint32_t* Bs = As + 4096;
        #pragma unroll
        for (int k8 = 0; k8 < 4; k8++) {
            uint4 af[4];
            uint2 bf[4];
            #pragma unroll
            for (int mt = 0; mt < 4; mt++)
                af[mt] = *(const uint4*)&As[((k8 * 8 + wy * 4 + mt) * 32 + lane) * 4];
            #pragma unroll
            for (int nt = 0; nt < 4; nt++)
                bf[nt] = *(const uint2*)&Bs[((k8 * 16 + wx * 4 + nt) * 32 + lane) * 2];
            #pragma unroll
            for (int mt = 0; mt < 4; mt++)
                #pragma unroll
                for (int nt = 0; nt < 4; nt++)
                    mma_tf32(acc[mt][nt], af[mt], bf[nt]);
        }
    };

    const int niter = K / 32;

    gload(0);
    sts(0);
    __syncthreads();

    for (int i = 0; i < niter; i++) {
        const bool more = (i + 1 < niter);
        if (more) gload((i + 1) * 32);
        compute(i & 1);
        if (more) sts((i + 1) & 1);
        __syncthreads();
    }

    const int rbase = bm + wy * 64 + (lane >> 2);
    const int cbase = bn + wx * 32 + (lane & 3) * 2;
    #pragma unroll
    for (int mt = 0; mt < 4; mt++) {
        #pragma unroll
        for (int nt = 0; nt < 4; nt++) {
            const int c = cbase + nt * 8;
            const float b0 = bias[c], b1 = bias[c + 1];
            const int r0 = rbase + mt * 16;
            const int r1 = r0 + 8;
            float v0 = acc[mt][nt][0] + b0;
            float v1 = acc[mt][nt][1] + b1;
            float v2 = acc[mt][nt][2] + b0;
            float v3 = acc[mt][nt][3] + b1;
            if (HAS_RES) {
                const float2 q0 = *(const float2*)&res[(size_t)r0 * N + c];
                const float2 q1 = *(const float2*)&res[(size_t)r1 * N + c];
                v0 += q0.x; v1 += q0.y; v2 += q1.x; v3 += q1.y;
            }
            if (RELU) {
                v0 = fmaxf(v0, 0.f); v1 = fmaxf(v1, 0.f);
                v2 = fmaxf(v2, 0.f); v3 = fmaxf(v3, 0.f);
            }
            *(float2*)&C[(size_t)r0 * N + c] = make_float2(v0, v1);
            *(float2*)&C[(size_t)r1 * N + c] = make_float2(v2, v3);
        }
    }
}

// =================== tf32 mma.sync flash attention, BN=128 =================
// CTA: 64 queries (one (b,h)), BN=128 keys per iteration, D=64.
// 8 warps: wy=wid&3 (m16 tile), wxh=wid>>2 (key/d half).
// smem: Qs 16KB (A-layout), Ks 32KB (B: n=key,k=d), Vs 32KB (B: n=d,k=key),
//       Ps 32KB (A: m=query,k=key), red[2][64], mk[128].
#define ATT_SMEM_BYTES ((4096 + 8192 + 8192 + 8192) * 4 + 128 * 4 + 128 * 4)

__global__ void __launch_bounds__(256)
attn_mma(const float* __restrict__ Q, const float* __restrict__ K,
         const float* __restrict__ V, const int* __restrict__ mask,
         float* __restrict__ O) {
    extern __shared__ char smraw[];
    uint32_t* Qs = (uint32_t*)smraw;
    uint32_t* Ks = Qs + 4096;
    uint32_t* Vs = Ks + 8192;
    uint32_t* Ps = Vs + 8192;
    float*    red = (float*)(Ps + 8192);   // [2][64]
    int*      mk  = (int*)(red + 128);     // [128]

    const int t = threadIdx.x, lane = t & 31, wid = t >> 5;
    const int wy = wid & 3, wxh = wid >> 2;
    const int q0 = blockIdx.x * 64;
    const int h  = blockIdx.y, b = blockIdx.z;
    const size_t base = (size_t)b * S_LEN * DM + (size_t)h * DK;

    // ---- stage Q once into A-fragment layout ----
    #pragma unroll
    for (int p = 0; p < 4; p++) {
        const int f = t + p * 256;
        const int row = f >> 4, g = f & 15;
        float4 v4 = *(const float4*)(Q + base + (size_t)(q0 + row) * DM + g * 4);
        const int mt = row >> 4, rr = row & 15;
        const int k8 = g >> 1, khi = g & 1;
        const int reg = (rr >> 3) + 2 * khi;
        const int bidx = ((k8 * 4 + mt) * 32 + (rr & 7) * 4) * 4 + reg;
        Qs[bidx +  0] = f2tf32(v4.x);
        Qs[bidx +  4] = f2tf32(v4.y);
        Qs[bidx +  8] = f2tf32(v4.z);
        Qs[bidx + 12] = f2tf32(v4.w);
    }

    const int rloc0 = wy * 16 + (lane >> 2);
    const int rloc1 = rloc0 + 8;

    float m0 = -INFINITY, m1 = -INFINITY, l0 = 0.f, l1 = 0.f;
    float o[4][4];
    #pragma unroll
    for (int i = 0; i < 4; i++)
        #pragma unroll
        for (int j = 0; j < 4; j++) o[i][j] = 0.f;

    for (int k0 = 0; k0 < S_LEN; k0 += 128) {
        // ---- stage K (B: n=key,k=d) and V (B: n=d,k=key); 8 float4 each ----
        #pragma unroll
        for (int p = 0; p < 8; p++) {
            const int f = t + p * 256;          // 2048 float4
            const int row = f >> 4, g = f & 15; // row=key 0..127, g: 4-float group of d
            float4 kv = *(const float4*)(K + base + (size_t)(k0 + row) * DM + g * 4);
            {
                const int nt = row >> 3, nr = row & 7;
                const int k8 = g >> 1, khi = g & 1;
                const int bidx = ((k8 * 16 + nt) * 32 + nr * 4) * 2 + khi;
                Ks[bidx + 0] = f2tf32(kv.x);
                Ks[bidx + 2] = f2tf32(kv.y);
                Ks[bidx + 4] = f2tf32(kv.z);
                Ks[bidx + 6] = f2tf32(kv.w);
            }
            float4 vv = *(const float4*)(V + base + (size_t)(k0 + row) * DM + g * 4);
            {
                const int k8 = row >> 3, klo = row & 3, khi = (row >> 2) & 1;
                const float vj[4] = {vv.x, vv.y, vv.z, vv.w};
                #pragma unroll
                for (int j = 0; j < 4; j++) {
                    const int n = g * 4 + j;
                    const int nt = n >> 3, nr = n & 7;
                    Vs[((k8 * 8 + nt) * 32 + nr * 4 + klo) * 2 + khi] = f2tf32(vj[j]);
                }
            }
        }
        if (t < 128) mk[t] = mask[(size_t)b * S_LEN + k0 + t];
        __syncthreads();

        // ---- S = Q K^T : warp covers 16 queries x 64 keys (wxh half) ----
        float s[8][4];
        #pragma unroll
        for (int nt = 0; nt < 8; nt++)
            #pragma unroll
            for (int r = 0; r < 4; r++) s[nt][r] = 0.f;
        #pragma unroll
        for (int k8 = 0; k8 < 8; k8++) {
            const uint4 af = *(const uint4*)&Qs[((k8 * 4 + wy) * 32 + lane) * 4];
            #pragma unroll
            for (int nt = 0; nt < 8; nt++) {
                const uint2 bf = *(const uint2*)&Ks[((k8 * 16 + wxh * 8 + nt) * 32 + lane) * 2];
                mma_tf32(s[nt], af, bf);
            }
        }

        // ---- mask + scale + row max ----
        float mx0 = -INFINITY, mx1 = -INFINITY;
        #pragma unroll
        for (int nt = 0; nt < 8; nt++) {
            const int c = wxh * 64 + nt * 8 + (lane & 3) * 2;
            const bool ma = mk[c] != 0, mb = mk[c + 1] != 0;
            s[nt][0] = ma ? s[nt][0] * 0.125f : -1e9f;
            s[nt][1] = mb ? s[nt][1] * 0.125f : -1e9f;
            s[nt][2] = ma ? s[nt][2] * 0.125f : -1e9f;
            s[nt][3] = mb ? s[nt][3] * 0.125f : -1e9f;
            mx0 = fmaxf(mx0, fmaxf(s[nt][0], s[nt][1]));
            mx1 = fmaxf(mx1, fmaxf(s[nt][2], s[nt][3]));
        }
        mx0 = fmaxf(mx0, __shfl_xor_sync(0xffffffffu, mx0, 1));
        mx0 = fmaxf(mx0, __shfl_xor_sync(0xffffffffu, mx0, 2));
        mx1 = fmaxf(mx1, __shfl_xor_sync(0xffffffffu, mx1, 1));
        mx1 = fmaxf(mx1, __shfl_xor_sync(0xffffffffu, mx1, 2));
        if ((lane & 3) == 0) {
            red[wxh * 64 + rloc0] = mx0;
            red[wxh * 64 + rloc1] = mx1;
        }
        __syncthreads();
        const float mn0 = fmaxf(m0, fmaxf(red[rloc0], red[64 + rloc0]));
        const float mn1 = fmaxf(m1, fmaxf(red[rloc1], red[64 + rloc1]));
        const float fac0 = __expf(m0 - mn0);
        const float fac1 = __expf(m1 - mn1);
        m0 = mn0; m1 = mn1;

        // ---- exp, write P (A-layout, k=key 0..127), update l, rescale O ----
        float sum0 = 0.f, sum1 = 0.f;
        #pragma unroll
        for (int nt = 0; nt < 8; nt++) {
            const float p0 = __expf(s[nt][0] - mn0);
            const float p1 = __expf(s[nt][1] - mn0);
            const float p2 = __expf(s[nt][2] - mn1);
            const float p3 = __expf(s[nt][3] - mn1);
            sum0 += p0 + p1;
            sum1 += p2 + p3;
            const int kk  = wxh * 64 + nt * 8 + (lane & 3) * 2;
            const int k8  = kk >> 3;
            const int kk7 = kk & 7;
            const int khi = kk7 >> 2, klo = kk7 & 3;
            const int idx = ((k8 * 4 + wy) * 32 + (lane >> 2) * 4 + klo) * 4 + 2 * khi;
            Ps[idx + 0] = f2tf32(p0);
            Ps[idx + 4] = f2tf32(p1);
            Ps[idx + 1] = f2tf32(p2);
            Ps[idx + 5] = f2tf32(p3);
        }
        #pragma unroll
        for (int nt = 0; nt < 4; nt++) {
            o[nt][0] *= fac0; o[nt][1] *= fac0;
            o[nt][2] *= fac1; o[nt][3] *= fac1;
        }
        l0 = l0 * fac0 + sum0;
        l1 = l1 * fac1 + sum1;
        __syncthreads();

        // ---- O += P V : warp covers 16 queries x 32 d (wxh half) ----
        #pragma unroll
        for (int k8 = 0; k8 < 16; k8++) {
            const uint4 af = *(const uint4*)&Ps[((k8 * 4 + wy) * 32 + lane) * 4];
            #pragma unroll
            for (int nt = 0; nt < 4; nt++) {
                const uint2 bf = *(const uint2*)&Vs[((k8 * 8 + wxh * 4 + nt) * 32 + lane) * 2];
                mma_tf32(o[nt], af, bf);
            }
        }
        __syncthreads();
    }

    // ---- final l reduction + store ----
    l0 += __shfl_xor_sync(0xffffffffu, l0, 1);
    l0 += __shfl_xor_sync(0xffffffffu, l0, 2);
    l1 += __shfl_xor_sync(0xffffffffu, l1, 1);
    l1 += __shfl_xor_sync(0xffffffffu, l1, 2);
    if ((lane & 3) == 0) {
        red[wxh * 64 + rloc0] = l0;
        red[wxh * 64 + rloc1] = l1;
    }
    __syncthreads();
    const float inv0 = 1.f / (red[rloc0] + red[64 + rloc0]);
    const float inv1 = 1.f / (red[rloc1] + red[64 + rloc1]);

    const size_t row0 = q0 + rloc0;
    #pragma unroll
    for (int nt = 0; nt < 4; nt++) {
        const int c = wxh * 32 + nt * 8 + (lane & 3) * 2;
        *(float2*)&O[base + row0 * DM + c] =
            make_float2(o[nt][0] * inv0, o[nt][1] * inv0);
        *(float2*)&O[base + (row0 + 8) * DM + c] =
            make_float2(o[nt][2] * inv1, o[nt][3] * inv1);
    }
}

// ---------------------------------------------------------------------------
extern "C" void kernel_launch(void* const* d_in, const int* in_sizes, int n_in,
                              void* d_out, int out_size) {
    const float* x      = (const float*)d_in[0];
    const int*   mask   = (const int*)  d_in[1];
    const float* wq     = (const float*)d_in[2];
    const float* bq     = (const float*)d_in[3];
    const float* wk     = (const float*)d_in[4];
    const float* bk     = (const float*)d_in[5];
    const float* wv     = (const float*)d_in[6];
    const float* bv     = (const float*)d_in[7];
    const float* wo     = (const float*)d_in[8];
    const float* bo     = (const float*)d_in[9];
    const float* w1     = (const float*)d_in[10];
    const float* b1     = (const float*)d_in[11];
    const float* w2     = (const float*)d_in[12];
    const float* b2     = (const float*)d_in[13];
    const float* alpha1 = (const float*)d_in[14];
    const float* beta1  = (const float*)d_in[15];
    const float* alpha2 = (const float*)d_in[16];
    const float* beta2  = (const float*)d_in[17];
    float* out = (float*)d_out;

    float *h, *q, *k, *v, *ctx, *x2, *ff;
    cudaGetSymbolAddress((void**)&h,   g_h);
    cudaGetSymbolAddress((void**)&q,   g_q);
    cudaGetSymbolAddress((void**)&k,   g_k);
    cudaGetSymbolAddress((void**)&v,   g_v);
    cudaGetSymbolAddress((void**)&ctx, g_ctx);
    cudaGetSymbolAddress((void**)&x2,  g_x2);
    cudaGetSymbolAddress((void**)&ff,  g_ff);

    cudaFuncSetAttribute(attn_mma, cudaFuncAttributeMaxDynamicSharedMemorySize, ATT_SMEM_BYTES);
    cudaFuncSetAttribute(gemm_mma<false, false>, cudaFuncAttributeMaxDynamicSharedMemorySize, GEMM_SMEM_BYTES);
    cudaFuncSetAttribute(gemm_mma<false, true>,  cudaFuncAttributeMaxDynamicSharedMemorySize, GEMM_SMEM_BYTES);
    cudaFuncSetAttribute(gemm_mma<true,  false>, cudaFuncAttributeMaxDynamicSharedMemorySize, GEMM_SMEM_BYTES);

    const dim3 g_qkv(DM / 128,  NTOK / 128);   // (6, 64)
    const dim3 g_ff1(DFF / 128, NTOK / 128);   // (24, 64)
    const dim3 attn_grid(S_LEN / 64, NH, BATCH);

    // 1. h = norm1(x)
    norm_kernel<<<NTOK, 256>>>(x, h, alpha1, beta1);
    // 2-4. q,k,v projections (tf32 mma.sync, double-buffered)
    gemm_mma<false, false><<<g_qkv, 256, GEMM_SMEM_BYTES>>>(h, wq, bq, nullptr, q, NTOK, DM, DM);
    gemm_mma<false, false><<<g_qkv, 256, GEMM_SMEM_BYTES>>>(h, wk, bk, nullptr, k, NTOK, DM, DM);
    gemm_mma<false, false><<<g_qkv, 256, GEMM_SMEM_BYTES>>>(h, wv, bv, nullptr, v, NTOK, DM, DM);
    // 5. attention -> ctx (tf32 mma.sync flash attention, BN=128)
    attn_mma<<<attn_grid, 256, ATT_SMEM_BYTES>>>(q, k, v, mask, ctx);
    // 6. x2 = x + ctx @ wo^T + bo
    gemm_mma<false, true><<<g_qkv, 256, GEMM_SMEM_BYTES>>>(ctx, wo, bo, x, x2, NTOK, DM, DM);
    // 7. h = norm2(x2)
    norm_kernel<<<NTOK, 256>>>(x2, h, alpha2, beta2);
    // 8. ff = relu(h @ w1^T + b1)
    gemm_mma<true, false><<<g_ff1, 256, GEMM_SMEM_BYTES>>>(h, w1, b1, nullptr, ff, NTOK, DFF, DM);
    // 9. out = x2 + ff @ w2^T + b2
    gemm_mma<false, true><<<g_qkv, 256, GEMM_SMEM_BYTES>>>(ff, w2, b2, x2, out, NTOK, DM, DFF);
}

// round 6
// speedup vs baseline: 1.0250x; 1.0250x over previous
#include <cuda_runtime.h>
#include <cstdint>
#include <math.h>

#define S_LEN 4096
#define BATCH 2
#define DM    768
#define DFF   3072
#define NH    12
#define DK    64
#define NTOK  (BATCH * S_LEN)

// ---------------- scratch (device globals: no allocation allowed) ----------
__device__ float g_h  [NTOK * DM];
__device__ float g_q  [NTOK * DM];
__device__ float g_k  [NTOK * DM];
__device__ float g_v  [NTOK * DM];
__device__ float g_ctx[NTOK * DM];
__device__ float g_x2 [NTOK * DM];
__device__ float g_ff [NTOK * DFF];

// ---------------- helpers --------------------------------------------------
__device__ __forceinline__ uint32_t f2tf32(float f) {
    uint32_t r; asm("cvt.rna.tf32.f32 %0, %1;" : "=r"(r) : "f"(f)); return r;
}

__device__ __forceinline__ void mma_tf32(float c[4], const uint4& a, const uint2& b) {
    asm volatile(
        "mma.sync.aligned.m16n8k8.row.col.f32.tf32.tf32.f32 "
        "{%0,%1,%2,%3}, {%4,%5,%6,%7}, {%8,%9}, {%0,%1,%2,%3};"
        : "+f"(c[0]), "+f"(c[1]), "+f"(c[2]), "+f"(c[3])
        : "r"(a.x), "r"(a.y), "r"(a.z), "r"(a.w), "r"(b.x), "r"(b.y));
}

// ---------------- layernorm-ish (scalar alpha/beta, ddof=1 std) -----------
__global__ void norm_kernel(const float* __restrict__ x, float* __restrict__ out,
                            const float* __restrict__ alpha, const float* __restrict__ beta) {
    const int row = blockIdx.x;
    const float* xr = x + (size_t)row * DM;
    float* orow = out + (size_t)row * DM;

    float v0 = xr[threadIdx.x];
    float v1 = xr[threadIdx.x + 256];
    float v2 = xr[threadIdx.x + 512];
    float s  = v0 + v1 + v2;
    float sq = v0 * v0 + v1 * v1 + v2 * v2;

    __shared__ float red0[8], red1[8];
    __shared__ float s_mean, s_scale, s_beta;
    #pragma unroll
    for (int o = 16; o > 0; o >>= 1) {
        s  += __shfl_xor_sync(0xffffffffu, s,  o);
        sq += __shfl_xor_sync(0xffffffffu, sq, o);
    }
    const int warp = threadIdx.x >> 5, lane = threadIdx.x & 31;
    if (lane == 0) { red0[warp] = s; red1[warp] = sq; }
    __syncthreads();
    if (threadIdx.x == 0) {
        float S = 0.f, SQ = 0.f;
        #pragma unroll
        for (int i = 0; i < 8; i++) { S += red0[i]; SQ += red1[i]; }
        const float mean = S / (float)DM;
        float var = (SQ - (float)DM * mean * mean) / (float)(DM - 1);
        var = fmaxf(var, 0.f);
        s_mean  = mean;
        s_scale = alpha[0] / (sqrtf(var) + 1e-6f);
        s_beta  = beta[0];
    }
    __syncthreads();
    const float mean = s_mean, scale = s_scale, bb = s_beta;
    orow[threadIdx.x]       = (v0 - mean) * scale + bb;
    orow[threadIdx.x + 256] = (v1 - mean) * scale + bb;
    orow[threadIdx.x + 512] = (v2 - mean) * scale + bb;
}

// =================== tf32 mma.sync GEMM, 2 CTAs/SM =========================
// C[M,N] = A[M,K] @ W[N,K]^T (+bias) (+res) (+relu)
// CTA tile 128x128, K-tile 32, 8 warps (64m x 32n each).
// Schedule: gload(i+1) -> sts(i+1) -> compute(i) -> sync.  Staging regs are
// live only gload->sts, so ptxas fits 128 regs for 2 CTAs/SM.
#define GEMM_SMEM_BYTES (2 * 8192 * 4)

template <bool RELU, bool HAS_RES>
__global__ void __launch_bounds__(256, 2)
gemm_mma(const float* __restrict__ A, const float* __restrict__ W,
         const float* __restrict__ bias, const float* __restrict__ res,
         float* __restrict__ C, int M, int N, int K) {
    extern __shared__ uint32_t gs[];   // [2][As 4096 | Bs 4096]

    const int t    = threadIdx.x;
    const int lane = t & 31;
    const int wid  = t >> 5;
    const int wy   = wid >> 2;
    const int wx   = wid & 3;
    const int bm   = blockIdx.y * 128;
    const int bn   = blockIdx.x * 128;

    const float* Ab = A + (size_t)bm * K;
    const float* Wb = W + (size_t)bn * K;

    int rowp[4], gp[4];
    #pragma unroll
    for (int p = 0; p < 4; p++) {
        const int f = t + p * 256;
        rowp[p] = f >> 3;
        gp[p]   = f & 7;
    }

    float acc[4][4][4];
    #pragma unroll
    for (int i = 0; i < 4; i++)
        #pragma unroll
        for (int j = 0; j < 4; j++)
            #pragma unroll
            for (int r = 0; r < 4; r++) acc[i][j][r] = 0.f;

    // load + permute + store in one pass: staging regs have minimal liveness
    auto stage_tile = [&](int k0, int buf) {
        uint32_t* As = gs + buf * 8192;
        uint32_t* Bs = As + 4096;
        #pragma unroll
        for (int p = 0; p < 4; p++) {
            const int row = rowp[p], g = gp[p];
            const int k8 = g >> 1, khi = g & 1;
            const float4 pa = *(const float4*)(Ab + (size_t)row * K + k0 + g * 4);
            {
                const int mt = row >> 4, rr = row & 15;
                const int reg = (rr >> 3) + 2 * khi;
                const int base = ((k8 * 8 + mt) * 32 + (rr & 7) * 4) * 4 + reg;
                As[base +  0] = f2tf32(pa.x);
                As[base +  4] = f2tf32(pa.y);
                As[base +  8] = f2tf32(pa.z);
                As[base + 12] = f2tf32(pa.w);
            }
            const float4 pb = *(const float4*)(Wb + (size_t)row * K + k0 + g * 4);
            {
                const int nt = row >> 3, nr = row & 7;
                const int base = ((k8 * 16 + nt) * 32 + nr * 4) * 2 + khi;
                Bs[base + 0] = f2tf32(pb.x);
                Bs[base + 2] = f2tf32(pb.y);
                Bs[base + 4] = f2tf32(pb.z);
                Bs[base + 6] = f2tf32(pb.w);
            }
        }
    };

    auto compute = [&](int buf) {
        const uint32_t* As = gs + buf * 8192;
        const uint32_t* Bs = As + 4096;
        #pragma unroll
        for (int k8 = 0; k8 < 4; k8++) {
            uint4 af[4];
            uint2 bf[4];
            #pragma unroll
            for (int mt = 0; mt < 4; mt++)
                af[mt] = *(const uint4*)&As[((k8 * 8 + wy * 4 + mt) * 32 + lane) * 4];
            #pragma unroll
            for (int nt = 0; nt < 4; nt++)
                bf[nt] = *(const uint2*)&Bs[((k8 * 16 + wx * 4 + nt) * 32 + lane) * 2];
            #pragma unroll
            for (int mt = 0; mt < 4; mt++)
                #pragma unroll
                for (int nt = 0; nt < 4; nt++)
                    mma_tf32(acc[mt][nt], af[mt], bf[nt]);
        }
    };

    const int niter = K / 32;

    stage_tile(0, 0);
    __syncthreads();

    for (int i = 0; i < niter; i++) {
        if (i + 1 < niter) stage_tile((i + 1) * 32, (i + 1) & 1);
        compute(i & 1);
        __syncthreads();
    }

    const int rbase = bm + wy * 64 + (lane >> 2);
    const int cbase = bn + wx * 32 + (lane & 3) * 2;
    #pragma unroll
    for (int mt = 0; mt < 4; mt++) {
        #pragma unroll
        for (int nt = 0; nt < 4; nt++) {
            const int c = cbase + nt * 8;
            const float b0 = bias[c], b1 = bias[c + 1];
            const int r0 = rbase + mt * 16;
            const int r1 = r0 + 8;
            float v0 = acc[mt][nt][0] + b0;
            float v1 = acc[mt][nt][1] + b1;
            float v2 = acc[mt][nt][2] + b0;
            float v3 = acc[mt][nt][3] + b1;
            if (HAS_RES) {
                const float2 q0 = *(const float2*)&res[(size_t)r0 * N + c];
                const float2 q1 = *(const float2*)&res[(size_t)r1 * N + c];
                v0 += q0.x; v1 += q0.y; v2 += q1.x; v3 += q1.y;
            }
            if (RELU) {
                v0 = fmaxf(v0, 0.f); v1 = fmaxf(v1, 0.f);
                v2 = fmaxf(v2, 0.f); v3 = fmaxf(v3, 0.f);
            }
            *(float2*)&C[(size_t)r0 * N + c] = make_float2(v0, v1);
            *(float2*)&C[(size_t)r1 * N + c] = make_float2(v2, v3);
        }
    }
}

// =================== tf32 mma.sync flash attention, BN=64, 2 CTAs/SM =======
// CTA: 64 queries (one (b,h)), BN=64 keys/iter, D=64.
// 8 warps: wy=wid&3 (m16 tile), wx=wid>>2 (n32 half).
#define ATT_SMEM (4 * 16384 + 128 * 4 + 64 * 4)

__global__ void __launch_bounds__(256, 2)
attn_mma(const float* __restrict__ Q, const float* __restrict__ K,
         const float* __restrict__ V, const int* __restrict__ mask,
         float* __restrict__ O) {
    extern __shared__ char smraw[];
    uint32_t* Qs = (uint32_t*)smraw;
    uint32_t* Ks = Qs + 4096;
    uint32_t* Vs = Ks + 4096;
    uint32_t* Ps = Vs + 4096;
    float*    red = (float*)(Ps + 4096);   // [2][64]
    int*      mk  = (int*)(red + 128);     // [64]

    const int t = threadIdx.x, lane = t & 31, wid = t >> 5;
    const int wy = wid & 3, wx = wid >> 2;
    const int q0 = blockIdx.x * 64;
    const int h  = blockIdx.y, b = blockIdx.z;
    const size_t base = (size_t)b * S_LEN * DM + (size_t)h * DK;

    // ---- stage Q once into A-fragment layout ----
    #pragma unroll
    for (int p = 0; p < 4; p++) {
        const int f = t + p * 256;          // 1024 float4
        const int row = f >> 4, g = f & 15;
        float4 v4 = *(const float4*)(Q + base + (size_t)(q0 + row) * DM + g * 4);
        const int mt = row >> 4, rr = row & 15;
        const int k8 = g >> 1, khi = g & 1;
        const int reg = (rr >> 3) + 2 * khi;
        const int bidx = ((k8 * 4 + mt) * 32 + (rr & 7) * 4) * 4 + reg;
        Qs[bidx +  0] = f2tf32(v4.x);
        Qs[bidx +  4] = f2tf32(v4.y);
        Qs[bidx +  8] = f2tf32(v4.z);
        Qs[bidx + 12] = f2tf32(v4.w);
    }

    const int rloc0 = wy * 16 + (lane >> 2);
    const int rloc1 = rloc0 + 8;

    float m0 = -INFINITY, m1 = -INFINITY, l0 = 0.f, l1 = 0.f;
    float o[4][4];
    #pragma unroll
    for (int i = 0; i < 4; i++)
        #pragma unroll
        for (int j = 0; j < 4; j++) o[i][j] = 0.f;

    for (int k0 = 0; k0 < S_LEN; k0 += 64) {
        // ---- stage K (B: n=key,k=d) and V (B: n=d,k=key) ----
        #pragma unroll
        for (int p = 0; p < 4; p++) {
            const int f = t + p * 256;
            const int row = f >> 4, g = f & 15;
            float4 kv = *(const float4*)(K + base + (size_t)(k0 + row) * DM + g * 4);
            {
                const int nt = row >> 3, nr = row & 7;
                const int k8 = g >> 1, khi = g & 1;
                const int bidx = ((k8 * 8 + nt) * 32 + nr * 4) * 2 + khi;
                Ks[bidx + 0] = f2tf32(kv.x);
                Ks[bidx + 2] = f2tf32(kv.y);
                Ks[bidx + 4] = f2tf32(kv.z);
                Ks[bidx + 6] = f2tf32(kv.w);
            }
            float4 vv = *(const float4*)(V + base + (size_t)(k0 + row) * DM + g * 4);
            {
                const int k8 = row >> 3, klo = row & 3, khi = (row >> 2) & 1;
                const float vj[4] = {vv.x, vv.y, vv.z, vv.w};
                #pragma unroll
                for (int j = 0; j < 4; j++) {
                    const int n = g * 4 + j;
                    const int nt = n >> 3, nr = n & 7;
                    Vs[((k8 * 8 + nt) * 32 + nr * 4 + klo) * 2 + khi] = f2tf32(vj[j]);
                }
            }
        }
        if (t < 64) mk[t] = mask[(size_t)b * S_LEN + k0 + t];
        __syncthreads();

        // ---- S = Q K^T ----
        float s[4][4];
        #pragma unroll
        for (int nt = 0; nt < 4; nt++)
            #pragma unroll
            for (int r = 0; r < 4; r++) s[nt][r] = 0.f;
        #pragma unroll
        for (int k8 = 0; k8 < 8; k8++) {
            const uint4 af = *(const uint4*)&Qs[((k8 * 4 + wy) * 32 + lane) * 4];
            #pragma unroll
            for (int nt = 0; nt < 4; nt++) {
                const uint2 bf = *(const uint2*)&Ks[((k8 * 8 + wx * 4 + nt) * 32 + lane) * 2];
                mma_tf32(s[nt], af, bf);
            }
        }

        // ---- mask + scale + row max ----
        float mx0 = -INFINITY, mx1 = -INFINITY;
        #pragma unroll
        for (int nt = 0; nt < 4; nt++) {
            const int c = wx * 32 + nt * 8 + (lane & 3) * 2;
            const bool ma = mk[c] != 0, mb = mk[c + 1] != 0;
            s[nt][0] = ma ? s[nt][0] * 0.125f : -1e9f;
            s[nt][1] = mb ? s[nt][1] * 0.125f : -1e9f;
            s[nt][2] = ma ? s[nt][2] * 0.125f : -1e9f;
            s[nt][3] = mb ? s[nt][3] * 0.125f : -1e9f;
            mx0 = fmaxf(mx0, fmaxf(s[nt][0], s[nt][1]));
            mx1 = fmaxf(mx1, fmaxf(s[nt][2], s[nt][3]));
        }
        mx0 = fmaxf(mx0, __shfl_xor_sync(0xffffffffu, mx0, 1));
        mx0 = fmaxf(mx0, __shfl_xor_sync(0xffffffffu, mx0, 2));
        mx1 = fmaxf(mx1, __shfl_xor_sync(0xffffffffu, mx1, 1));
        mx1 = fmaxf(mx1, __shfl_xor_sync(0xffffffffu, mx1, 2));
        if ((lane & 3) == 0) {
            red[wx * 64 + rloc0] = mx0;
            red[wx * 64 + rloc1] = mx1;
        }
        __syncthreads();
        const float mn0 = fmaxf(m0, fmaxf(red[rloc0], red[64 + rloc0]));
        const float mn1 = fmaxf(m1, fmaxf(red[rloc1], red[64 + rloc1]));
        const float fac0 = __expf(m0 - mn0);
        const float fac1 = __expf(m1 - mn1);
        m0 = mn0; m1 = mn1;

        // ---- exp, write P into A-layout, update l, rescale O ----
        float sum0 = 0.f, sum1 = 0.f;
        #pragma unroll
        for (int nt = 0; nt < 4; nt++) {
            const float p0 = __expf(s[nt][0] - mn0);
            const float p1 = __expf(s[nt][1] - mn0);
            const float p2 = __expf(s[nt][2] - mn1);
            const float p3 = __expf(s[nt][3] - mn1);
            sum0 += p0 + p1;
            sum1 += p2 + p3;
            const int kk  = wx * 32 + nt * 8 + (lane & 3) * 2;
            const int k8  = kk >> 3;
            const int kk7 = kk & 7;
            const int khi = kk7 >> 2, klo = kk7 & 3;
            const int idx = ((k8 * 4 + wy) * 32 + (lane >> 2) * 4 + klo) * 4 + 2 * khi;
            Ps[idx + 0] = f2tf32(p0);
            Ps[idx + 4] = f2tf32(p1);
            Ps[idx + 1] = f2tf32(p2);
            Ps[idx + 5] = f2tf32(p3);
            o[nt][0] *= fac0; o[nt][1] *= fac0;
            o[nt][2] *= fac1; o[nt][3] *= fac1;
        }
        l0 = l0 * fac0 + sum0;
        l1 = l1 * fac1 + sum1;
        __syncthreads();

        // ---- O += P V ----
        #pragma unroll
        for (int k8 = 0; k8 < 8; k8++) {
            const uint4 af = *(const uint4*)&Ps[((k8 * 4 + wy) * 32 + lane) * 4];
            #pragma unroll
            for (int nt = 0; nt < 4; nt++) {
                const uint2 bf = *(const uint2*)&Vs[((k8 * 8 + wx * 4 + nt) * 32 + lane) * 2];
                mma_tf32(o[nt], af, bf);
            }
        }
        __syncthreads();
    }

    // ---- final l reduction + store ----
    l0 += __shfl_xor_sync(0xffffffffu, l0, 1);
    l0 += __shfl_xor_sync(0xffffffffu, l0, 2);
    l1 += __shfl_xor_sync(0xffffffffu, l1, 1);
    l1 += __shfl_xor_sync(0xffffffffu, l1, 2);
    if ((lane & 3) == 0) {
        red[wx * 64 + rloc0] = l0;
        red[wx * 64 + rloc1] = l1;
    }
    __syncthreads();
    const float inv0 = 1.f / (red[rloc0] + red[64 + rloc0]);
    const float inv1 = 1.f / (red[rloc1] + red[64 + rloc1]);

    const size_t row0 = q0 + rloc0;
    #pragma unroll
    for (int nt = 0; nt < 4; nt++) {
        const int c = wx * 32 + nt * 8 + (lane & 3) * 2;
        *(float2*)&O[base + row0 * DM + c] =
            make_float2(o[nt][0] * inv0, o[nt][1] * inv0);
        *(float2*)&O[base + (row0 + 8) * DM + c] =
            make_float2(o[nt][2] * inv1, o[nt][3] * inv1);
    }
}

// ---------------------------------------------------------------------------
extern "C" void kernel_launch(void* const* d_in, const int* in_sizes, int n_in,
                              void* d_out, int out_size) {
    const float* x      = (const float*)d_in[0];
    const int*   mask   = (const int*)  d_in[1];
    const float* wq     = (const float*)d_in[2];
    const float* bq     = (const float*)d_in[3];
    const float* wk     = (const float*)d_in[4];
    const float* bk     = (const float*)d_in[5];
    const float* wv     = (const float*)d_in[6];
    const float* bv     = (const float*)d_in[7];
    const float* wo     = (const float*)d_in[8];
    const float* bo     = (const float*)d_in[9];
    const float* w1     = (const float*)d_in[10];
    const float* b1     = (const float*)d_in[11];
    const float* w2     = (const float*)d_in[12];
    const float* b2     = (const float*)d_in[13];
    const float* alpha1 = (const float*)d_in[14];
    const float* beta1  = (const float*)d_in[15];
    const float* alpha2 = (const float*)d_in[16];
    const float* beta2  = (const float*)d_in[17];
    float* out = (float*)d_out;

    float *h, *q, *k, *v, *ctx, *x2, *ff;
    cudaGetSymbolAddress((void**)&h,   g_h);
    cudaGetSymbolAddress((void**)&q,   g_q);
    cudaGetSymbolAddress((void**)&k,   g_k);
    cudaGetSymbolAddress((void**)&v,   g_v);
    cudaGetSymbolAddress((void**)&ctx, g_ctx);
    cudaGetSymbolAddress((void**)&x2,  g_x2);
    cudaGetSymbolAddress((void**)&ff,  g_ff);

    cudaFuncSetAttribute(attn_mma, cudaFuncAttributeMaxDynamicSharedMemorySize, ATT_SMEM);
    cudaFuncSetAttribute(gemm_mma<false, false>, cudaFuncAttributeMaxDynamicSharedMemorySize, GEMM_SMEM_BYTES);
    cudaFuncSetAttribute(gemm_mma<false, true>,  cudaFuncAttributeMaxDynamicSharedMemorySize, GEMM_SMEM_BYTES);
    cudaFuncSetAttribute(gemm_mma<true,  false>, cudaFuncAttributeMaxDynamicSharedMemorySize, GEMM_SMEM_BYTES);

    const dim3 g_qkv(DM / 128,  NTOK / 128);   // (6, 64)
    const dim3 g_ff1(DFF / 128, NTOK / 128);   // (24, 64)
    const dim3 attn_grid(S_LEN / 64, NH, BATCH);

    // 1. h = norm1(x)
    norm_kernel<<<NTOK, 256>>>(x, h, alpha1, beta1);
    // 2-4. q,k,v projections (tf32 mma.sync, 2 CTAs/SM)
    gemm_mma<false, false><<<g_qkv, 256, GEMM_SMEM_BYTES>>>(h, wq, bq, nullptr, q, NTOK, DM, DM);
    gemm_mma<false, false><<<g_qkv, 256, GEMM_SMEM_BYTES>>>(h, wk, bk, nullptr, k, NTOK, DM, DM);
    gemm_mma<false, false><<<g_qkv, 256, GEMM_SMEM_BYTES>>>(h, wv, bv, nullptr, v, NTOK, DM, DM);
    // 5. attention -> ctx (tf32 mma.sync flash attention, BN=64, 2 CTAs/SM)
    attn_mma<<<attn_grid, 256, ATT_SMEM>>>(q, k, v, mask, ctx);
    // 6. x2 = x + ctx @ wo^T + bo
    gemm_mma<false, true><<<g_qkv, 256, GEMM_SMEM_BYTES>>>(ctx, wo, bo, x, x2, NTOK, DM, DM);
    // 7. h = norm2(x2)
    norm_kernel<<<NTOK, 256>>>(x2, h, alpha2, beta2);
    // 8. ff = relu(h @ w1^T + b1)
    gemm_mma<true, false><<<g_ff1, 256, GEMM_SMEM_BYTES>>>(h, w1, b1, nullptr, ff, NTOK, DFF, DM);
    // 9. out = x2 + ff @ w2^T + b2
    gemm_mma<false, true><<<g_qkv, 256, GEMM_SMEM_BYTES>>>(ff, w2, b2, x2, out, NTOK, DM, DFF);
}

// round 7
// speedup vs baseline: 1.5674x; 1.5291x over previous
#include <cuda_runtime.h>
#include <cuda_fp16.h>
#include <cstdint>
#include <math.h>

#define S_LEN 4096
#define BATCH 2
#define DM    768
#define DFF   3072
#define NH    12
#define DK    64
#define NTOK  (BATCH * S_LEN)

// ---------------- scratch (device globals: no allocation allowed) ----------
__device__ float g_h  [NTOK * DM];
__device__ float g_q  [NTOK * DM];
__device__ float g_k  [NTOK * DM];
__device__ float g_v  [NTOK * DM];
__device__ float g_ctx[NTOK * DM];
__device__ float g_x2 [NTOK * DM];
__device__ float g_ff [NTOK * DFF];

// ---------------- helpers --------------------------------------------------
__device__ __forceinline__ uint32_t pack_h2(float lo, float hi) {
    uint32_t r; asm("cvt.rn.f16x2.f32 %0, %1, %2;" : "=r"(r) : "f"(hi), "f"(lo)); return r;
}

__device__ __forceinline__ void mma_f16(float c[4], const uint4& a, const uint2& b) {
    asm volatile(
        "mma.sync.aligned.m16n8k16.row.col.f32.f16.f16.f32 "
        "{%0,%1,%2,%3}, {%4,%5,%6,%7}, {%8,%9}, {%0,%1,%2,%3};"
        : "+f"(c[0]), "+f"(c[1]), "+f"(c[2]), "+f"(c[3])
        : "r"(a.x), "r"(a.y), "r"(a.z), "r"(a.w), "r"(b.x), "r"(b.y));
}

// ---------------- layernorm-ish (scalar alpha/beta, ddof=1 std) -----------
__global__ void norm_kernel(const float* __restrict__ x, float* __restrict__ out,
                            const float* __restrict__ alpha, const float* __restrict__ beta) {
    const int row = blockIdx.x;
    const float* xr = x + (size_t)row * DM;
    float* orow = out + (size_t)row * DM;

    float v0 = xr[threadIdx.x];
    float v1 = xr[threadIdx.x + 256];
    float v2 = xr[threadIdx.x + 512];
    float s  = v0 + v1 + v2;
    float sq = v0 * v0 + v1 * v1 + v2 * v2;

    __shared__ float red0[8], red1[8];
    __shared__ float s_mean, s_scale, s_beta;
    #pragma unroll
    for (int o = 16; o > 0; o >>= 1) {
        s  += __shfl_xor_sync(0xffffffffu, s,  o);
        sq += __shfl_xor_sync(0xffffffffu, sq, o);
    }
    const int warp = threadIdx.x >> 5, lane = threadIdx.x & 31;
    if (lane == 0) { red0[warp] = s; red1[warp] = sq; }
    __syncthreads();
    if (threadIdx.x == 0) {
        float S = 0.f, SQ = 0.f;
        #pragma unroll
        for (int i = 0; i < 8; i++) { S += red0[i]; SQ += red1[i]; }
        const float mean = S / (float)DM;
        float var = (SQ - (float)DM * mean * mean) / (float)(DM - 1);
        var = fmaxf(var, 0.f);
        s_mean  = mean;
        s_scale = alpha[0] / (sqrtf(var) + 1e-6f);
        s_beta  = beta[0];
    }
    __syncthreads();
    const float mean = s_mean, scale = s_scale, bb = s_beta;
    orow[threadIdx.x]       = (v0 - mean) * scale + bb;
    orow[threadIdx.x + 256] = (v1 - mean) * scale + bb;
    orow[threadIdx.x + 512] = (v2 - mean) * scale + bb;
}

// =================== fp16 m16n8k16 mma GEMM ================================
// C[M,N] = A[M,K] @ W[N,K]^T (+bias) (+res) (+relu)
// CTA 128x128, K-tile 32 (2 x k16), 8 warps (64m x 32n each), double-buffered.
// smem holds f16x2 tiles pre-permuted into fragment layout:
//   A tile (kt,mt): 32 lanes x 4 u32   B tile (kt,nt): 32 lanes x 2 u32
#define GEMM_SMEM_BYTES (2 * 4096 * 4)

template <bool RELU, bool HAS_RES>
__global__ void __launch_bounds__(256, 2)
gemm_mma(const float* __restrict__ A, const float* __restrict__ W,
         const float* __restrict__ bias, const float* __restrict__ res,
         float* __restrict__ C, int M, int N, int K) {
    extern __shared__ uint32_t gs[];   // [2][As 2048 | Bs 2048]

    const int t    = threadIdx.x;
    const int lane = t & 31;
    const int wid  = t >> 5;
    const int wy   = wid >> 2;
    const int wx   = wid & 3;
    const int bm   = blockIdx.y * 128;
    const int bn   = blockIdx.x * 128;

    const float* Ab = A + (size_t)bm * K;
    const float* Wb = W + (size_t)bn * K;

    int rowp[4], gp[4];
    #pragma unroll
    for (int p = 0; p < 4; p++) {
        const int f = t + p * 256;
        rowp[p] = f >> 3;
        gp[p]   = f & 7;
    }

    float acc[4][4][4];
    #pragma unroll
    for (int i = 0; i < 4; i++)
        #pragma unroll
        for (int j = 0; j < 4; j++)
            #pragma unroll
            for (int r = 0; r < 4; r++) acc[i][j][r] = 0.f;

    auto stage_tile = [&](int k0, int buf) {
        uint32_t* As = gs + buf * 4096;
        uint32_t* Bs = As + 2048;
        #pragma unroll
        for (int p = 0; p < 4; p++) {
            const int row = rowp[p], g = gp[p];
            const int kt = g >> 2, rhi = (g >> 1) & 1, llo = g & 1;
            const float4 pa = *(const float4*)(Ab + (size_t)row * K + k0 + g * 4);
            {
                const int mt = row >> 4, rr = row & 15;
                const int reg = (rr >> 3) + 2 * rhi;
                const int base = ((kt * 8 + mt) * 32 + (rr & 7) * 4 + 2 * llo) * 4 + reg;
                As[base]     = pack_h2(pa.x, pa.y);
                As[base + 4] = pack_h2(pa.z, pa.w);
            }
            const float4 pb = *(const float4*)(Wb + (size_t)row * K + k0 + g * 4);
            {
                const int nt = row >> 3, nr = row & 7;
                const int base = ((kt * 16 + nt) * 32 + nr * 4 + 2 * llo) * 2 + rhi;
                Bs[base]     = pack_h2(pb.x, pb.y);
                Bs[base + 2] = pack_h2(pb.z, pb.w);
            }
        }
    };

    auto compute = [&](int buf) {
        const uint32_t* As = gs + buf * 4096;
        const uint32_t* Bs = As + 2048;
        #pragma unroll
        for (int kt = 0; kt < 2; kt++) {
            uint4 af[4];
            uint2 bf[4];
            #pragma unroll
            for (int mt = 0; mt < 4; mt++)
                af[mt] = *(const uint4*)&As[((kt * 8 + wy * 4 + mt) * 32 + lane) * 4];
            #pragma unroll
            for (int nt = 0; nt < 4; nt++)
                bf[nt] = *(const uint2*)&Bs[((kt * 16 + wx * 4 + nt) * 32 + lane) * 2];
            #pragma unroll
            for (int mt = 0; mt < 4; mt++)
                #pragma unroll
                for (int nt = 0; nt < 4; nt++)
                    mma_f16(acc[mt][nt], af[mt], bf[nt]);
        }
    };

    const int niter = K / 32;

    stage_tile(0, 0);
    __syncthreads();

    for (int i = 0; i < niter; i++) {
        if (i + 1 < niter) stage_tile((i + 1) * 32, (i + 1) & 1);
        compute(i & 1);
        __syncthreads();
    }

    const int rbase = bm + wy * 64 + (lane >> 2);
    const int cbase = bn + wx * 32 + (lane & 3) * 2;
    #pragma unroll
    for (int mt = 0; mt < 4; mt++) {
        #pragma unroll
        for (int nt = 0; nt < 4; nt++) {
            const int c = cbase + nt * 8;
            const float b0 = bias[c], b1 = bias[c + 1];
            const int r0 = rbase + mt * 16;
            const int r1 = r0 + 8;
            float v0 = acc[mt][nt][0] + b0;
            float v1 = acc[mt][nt][1] + b1;
            float v2 = acc[mt][nt][2] + b0;
            float v3 = acc[mt][nt][3] + b1;
            if (HAS_RES) {
                const float2 q0 = *(const float2*)&res[(size_t)r0 * N + c];
                const float2 q1 = *(const float2*)&res[(size_t)r1 * N + c];
                v0 += q0.x; v1 += q0.y; v2 += q1.x; v3 += q1.y;
            }
            if (RELU) {
                v0 = fmaxf(v0, 0.f); v1 = fmaxf(v1, 0.f);
                v2 = fmaxf(v2, 0.f); v3 = fmaxf(v3, 0.f);
            }
            *(float2*)&C[(size_t)r0 * N + c] = make_float2(v0, v1);
            *(float2*)&C[(size_t)r1 * N + c] = make_float2(v2, v3);
        }
    }
}

// =================== fp16 mma flash attention, BN=64 =======================
// CTA: 64 queries (one (b,h)), BN=64 keys/iter, D=64.
// 8 warps: wy=wid&3 (m16 tile), wx=wid>>2 (n32 half).
__global__ void __launch_bounds__(256, 2)
attn_mma(const float* __restrict__ Q, const float* __restrict__ K,
         const float* __restrict__ V, const int* __restrict__ mask,
         float* __restrict__ O) {
    __shared__ uint32_t Qs[2048];   // A-layout: 4 kt x 4 mt
    __shared__ uint32_t Ks[2048];   // B-layout: 4 kt(d) x 8 nt(key)
    __shared__ uint32_t Vs[2048];   // B-layout: 4 kt(key) x 8 nt(d)
    __shared__ uint32_t Ps[2048];   // A-layout: 4 kt(key) x 4 mt(query)
    __shared__ float    red[128];   // [2][64]
    __shared__ int      mk[64];

    const int t = threadIdx.x, lane = t & 31, wid = t >> 5;
    const int wy = wid & 3, wx = wid >> 2;
    const int q0 = blockIdx.x * 64;
    const int h  = blockIdx.y, b = blockIdx.z;
    const size_t base = (size_t)b * S_LEN * DM + (size_t)h * DK;

    // ---- stage Q once into A-fragment layout (f16x2) ----
    #pragma unroll
    for (int p = 0; p < 4; p++) {
        const int f = t + p * 256;          // 1024 float4
        const int row = f >> 4, g = f & 15;
        float4 v4 = *(const float4*)(Q + base + (size_t)(q0 + row) * DM + g * 4);
        const int mt = row >> 4, rr = row & 15;
        const int kt = g >> 2, rhi = (g >> 1) & 1, llo = g & 1;
        const int reg = (rr >> 3) + 2 * rhi;
        const int bidx = ((kt * 4 + mt) * 32 + (rr & 7) * 4 + 2 * llo) * 4 + reg;
        Qs[bidx]     = pack_h2(v4.x, v4.y);
        Qs[bidx + 4] = pack_h2(v4.z, v4.w);
    }

    const int rloc0 = wy * 16 + (lane >> 2);
    const int rloc1 = rloc0 + 8;

    float m0 = -INFINITY, m1 = -INFINITY, l0 = 0.f, l1 = 0.f;
    float o[4][4];
    #pragma unroll
    for (int i = 0; i < 4; i++)
        #pragma unroll
        for (int j = 0; j < 4; j++) o[i][j] = 0.f;

    for (int k0 = 0; k0 < S_LEN; k0 += 64) {
        // ---- stage K (B: n=key,k=d) and V (B: n=d,k=key) ----
        #pragma unroll
        for (int p = 0; p < 4; p++) {
            const int f = t + p * 256;
            const int row = f >> 4, g = f & 15;
            float4 kv = *(const float4*)(K + base + (size_t)(k0 + row) * DM + g * 4);
            {
                const int nt = row >> 3, nr = row & 7;
                const int kt = g >> 2, rhi = (g >> 1) & 1, llo = g & 1;
                const int bidx = ((kt * 8 + nt) * 32 + nr * 4 + 2 * llo) * 2 + rhi;
                Ks[bidx]     = pack_h2(kv.x, kv.y);
                Ks[bidx + 2] = pack_h2(kv.z, kv.w);
            }
            float4 vv = *(const float4*)(V + base + (size_t)(k0 + row) * DM + g * 4);
            {
                // V: k-dim = key (row), n-dim = d. 16-bit scatter stores.
                half* Vh = (half*)Vs;
                const int ktv  = row >> 4;
                const int regv = (row >> 3) & 1;
                const int lprt = (row >> 1) & 3;
                const int klo  = row & 1;
                const float vj[4] = {vv.x, vv.y, vv.z, vv.w};
                #pragma unroll
                for (int j = 0; j < 4; j++) {
                    const int n = g * 4 + j;
                    const int nt = n >> 3, nr = n & 7;
                    Vh[(((ktv * 8 + nt) * 32 + nr * 4 + lprt) * 2 + regv) * 2 + klo] =
                        __float2half_rn(vj[j]);
                }
            }
        }
        if (t < 64) mk[t] = mask[(size_t)b * S_LEN + k0 + t];
        __syncthreads();

        // ---- S = Q K^T ----
        float s[4][4];
        #pragma unroll
        for (int nt = 0; nt < 4; nt++)
            #pragma unroll
            for (int r = 0; r < 4; r++) s[nt][r] = 0.f;
        #pragma unroll
        for (int kt = 0; kt < 4; kt++) {
            const uint4 af = *(const uint4*)&Qs[((kt * 4 + wy) * 32 + lane) * 4];
            #pragma unroll
            for (int nt = 0; nt < 4; nt++) {
                const uint2 bf = *(const uint2*)&Ks[((kt * 8 + wx * 4 + nt) * 32 + lane) * 2];
                mma_f16(s[nt], af, bf);
            }
        }

        // ---- mask + scale + row max ----
        float mx0 = -INFINITY, mx1 = -INFINITY;
        #pragma unroll
        for (int nt = 0; nt < 4; nt++) {
            const int c = wx * 32 + nt * 8 + (lane & 3) * 2;
            const bool ma = mk[c] != 0, mb = mk[c + 1] != 0;
            s[nt][0] = ma ? s[nt][0] * 0.125f : -1e9f;
            s[nt][1] = mb ? s[nt][1] * 0.125f : -1e9f;
            s[nt][2] = ma ? s[nt][2] * 0.125f : -1e9f;
            s[nt][3] = mb ? s[nt][3] * 0.125f : -1e9f;
            mx0 = fmaxf(mx0, fmaxf(s[nt][0], s[nt][1]));
            mx1 = fmaxf(mx1, fmaxf(s[nt][2], s[nt][3]));
        }
        mx0 = fmaxf(mx0, __shfl_xor_sync(0xffffffffu, mx0, 1));
        mx0 = fmaxf(mx0, __shfl_xor_sync(0xffffffffu, mx0, 2));
        mx1 = fmaxf(mx1, __shfl_xor_sync(0xffffffffu, mx1, 1));
        mx1 = fmaxf(mx1, __shfl_xor_sync(0xffffffffu, mx1, 2));
        if ((lane & 3) == 0) {
            red[wx * 64 + rloc0] = mx0;
            red[wx * 64 + rloc1] = mx1;
        }
        __syncthreads();
        const float mn0 = fmaxf(m0, fmaxf(red[rloc0], red[64 + rloc0]));
        const float mn1 = fmaxf(m1, fmaxf(red[rloc1], red[64 + rloc1]));
        const float fac0 = __expf(m0 - mn0);
        const float fac1 = __expf(m1 - mn1);
        m0 = mn0; m1 = mn1;

        // ---- exp, write P (A-layout, packed f16x2), update l, rescale O ----
        float sum0 = 0.f, sum1 = 0.f;
        const int lane_t = (lane >> 2) * 4 + (lane & 3);
        #pragma unroll
        for (int nt = 0; nt < 4; nt++) {
            const float p0 = __expf(s[nt][0] - mn0);
            const float p1 = __expf(s[nt][1] - mn0);
            const float p2 = __expf(s[nt][2] - mn1);
            const float p3 = __expf(s[nt][3] - mn1);
            sum0 += p0 + p1;
            sum1 += p2 + p3;
            const int kt = wx * 2 + (nt >> 1);
            const int idx = ((kt * 4 + wy) * 32 + lane_t) * 4 + 2 * (nt & 1);
            Ps[idx]     = pack_h2(p0, p1);   // rloc0 row, k=c,c+1
            Ps[idx + 1] = pack_h2(p2, p3);   // rloc1 row
            o[nt][0] *= fac0; o[nt][1] *= fac0;
            o[nt][2] *= fac1; o[nt][3] *= fac1;
        }
        l0 = l0 * fac0 + sum0;
        l1 = l1 * fac1 + sum1;
        __syncthreads();

        // ---- O += P V ----
        #pragma unroll
        for (int kt = 0; kt < 4; kt++) {
            const uint4 af = *(const uint4*)&Ps[((kt * 4 + wy) * 32 + lane) * 4];
            #pragma unroll
            for (int nt = 0; nt < 4; nt++) {
                const uint2 bf = *(const uint2*)&Vs[((kt * 8 + wx * 4 + nt) * 32 + lane) * 2];
                mma_f16(o[nt], af, bf);
            }
        }
        __syncthreads();
    }

    // ---- final l reduction + store ----
    l0 += __shfl_xor_sync(0xffffffffu, l0, 1);
    l0 += __shfl_xor_sync(0xffffffffu, l0, 2);
    l1 += __shfl_xor_sync(0xffffffffu, l1, 1);
    l1 += __shfl_xor_sync(0xffffffffu, l1, 2);
    if ((lane & 3) == 0) {
        red[wx * 64 + rloc0] = l0;
        red[wx * 64 + rloc1] = l1;
    }
    __syncthreads();
    const float inv0 = 1.f / (red[rloc0] + red[64 + rloc0]);
    const float inv1 = 1.f / (red[rloc1] + red[64 + rloc1]);

    const size_t row0 = q0 + rloc0;
    #pragma unroll
    for (int nt = 0; nt < 4; nt++) {
        const int c = wx * 32 + nt * 8 + (lane & 3) * 2;
        *(float2*)&O[base + row0 * DM + c] =
            make_float2(o[nt][0] * inv0, o[nt][1] * inv0);
        *(float2*)&O[base + (row0 + 8) * DM + c] =
            make_float2(o[nt][2] * inv1, o[nt][3] * inv1);
    }
}

// ---------------------------------------------------------------------------
extern "C" void kernel_launch(void* const* d_in, const int* in_sizes, int n_in,
                              void* d_out, int out_size) {
    const float* x      = (const float*)d_in[0];
    const int*   mask   = (const int*)  d_in[1];
    const float* wq     = (const float*)d_in[2];
    const float* bq     = (const float*)d_in[3];
    const float* wk     = (const float*)d_in[4];
    const float* bk     = (const float*)d_in[5];
    const float* wv     = (const float*)d_in[6];
    const float* bv     = (const float*)d_in[7];
    const float* wo     = (const float*)d_in[8];
    const float* bo     = (const float*)d_in[9];
    const float* w1     = (const float*)d_in[10];
    const float* b1     = (const float*)d_in[11];
    const float* w2     = (const float*)d_in[12];
    const float* b2     = (const float*)d_in[13];
    const float* alpha1 = (const float*)d_in[14];
    const float* beta1  = (const float*)d_in[15];
    const float* alpha2 = (const float*)d_in[16];
    const float* beta2  = (const float*)d_in[17];
    float* out = (float*)d_out;

    float *h, *q, *k, *v, *ctx, *x2, *ff;
    cudaGetSymbolAddress((void**)&h,   g_h);
    cudaGetSymbolAddress((void**)&q,   g_q);
    cudaGetSymbolAddress((void**)&k,   g_k);
    cudaGetSymbolAddress((void**)&v,   g_v);
    cudaGetSymbolAddress((void**)&ctx, g_ctx);
    cudaGetSymbolAddress((void**)&x2,  g_x2);
    cudaGetSymbolAddress((void**)&ff,  g_ff);

    cudaFuncSetAttribute(gemm_mma<false, false>, cudaFuncAttributeMaxDynamicSharedMemorySize, GEMM_SMEM_BYTES);
    cudaFuncSetAttribute(gemm_mma<false, true>,  cudaFuncAttributeMaxDynamicSharedMemorySize, GEMM_SMEM_BYTES);
    cudaFuncSetAttribute(gemm_mma<true,  false>, cudaFuncAttributeMaxDynamicSharedMemorySize, GEMM_SMEM_BYTES);

    const dim3 g_qkv(DM / 128,  NTOK / 128);   // (6, 64)
    const dim3 g_ff1(DFF / 128, NTOK / 128);   // (24, 64)
    const dim3 attn_grid(S_LEN / 64, NH, BATCH);

    // 1. h = norm1(x)
    norm_kernel<<<NTOK, 256>>>(x, h, alpha1, beta1);
    // 2-4. q,k,v projections (fp16 m16n8k16 mma)
    gemm_mma<false, false><<<g_qkv, 256, GEMM_SMEM_BYTES>>>(h, wq, bq, nullptr, q, NTOK, DM, DM);
    gemm_mma<false, false><<<g_qkv, 256, GEMM_SMEM_BYTES>>>(h, wk, bk, nullptr, k, NTOK, DM, DM);
    gemm_mma<false, false><<<g_qkv, 256, GEMM_SMEM_BYTES>>>(h, wv, bv, nullptr, v, NTOK, DM, DM);
    // 5. attention -> ctx (fp16 mma flash attention)
    attn_mma<<<attn_grid, 256>>>(q, k, v, mask, ctx);
    // 6. x2 = x + ctx @ wo^T + bo
    gemm_mma<false, true><<<g_qkv, 256, GEMM_SMEM_BYTES>>>(ctx, wo, bo, x, x2, NTOK, DM, DM);
    // 7. h = norm2(x2)
    norm_kernel<<<NTOK, 256>>>(x2, h, alpha2, beta2);
    // 8. ff = relu(h @ w1^T + b1)
    gemm_mma<true, false><<<g_ff1, 256, GEMM_SMEM_BYTES>>>(h, w1, b1, nullptr, ff, NTOK, DFF, DM);
    // 9. out = x2 + ff @ w2^T + b2
    gemm_mma<false, true><<<g_qkv, 256, GEMM_SMEM_BYTES>>>(ff, w2, b2, x2, out, NTOK, DM, DFF);
}

// round 8
// speedup vs baseline: 2.2881x; 1.4599x over previous
#include <cuda_runtime.h>
#include <cuda_fp16.h>
#include <cstdint>
#include <math.h>

#define S_LEN 4096
#define BATCH 2
#define DM    768
#define DFF   3072
#define NH    12
#define DK    64
#define NTOK  (BATCH * S_LEN)

// ---------------- scratch (device globals: no allocation allowed) ----------
__device__ __half g_h  [NTOK * DM];
__device__ __half g_q  [NTOK * DM];
__device__ __half g_k  [NTOK * DM];
__device__ __half g_v  [NTOK * DM];
__device__ __half g_ctx[NTOK * DM];
__device__ float  g_x2 [NTOK * DM];
__device__ __half g_ff [NTOK * DFF];
// weight fragments (u32 = f16x2), layout [ntile][ktile][2048]
__device__ uint32_t g_wqf[DM * DM / 2];
__device__ uint32_t g_wkf[DM * DM / 2];
__device__ uint32_t g_wvf[DM * DM / 2];
__device__ uint32_t g_wof[DM * DM / 2];
__device__ uint32_t g_w1f[DFF * DM / 2];
__device__ uint32_t g_w2f[DM * DFF / 2];

// ---------------- helpers --------------------------------------------------
__device__ __forceinline__ uint32_t pack_h2(float lo, float hi) {
    uint32_t r; asm("cvt.rn.f16x2.f32 %0, %1, %2;" : "=r"(r) : "f"(hi), "f"(lo)); return r;
}

__device__ __forceinline__ void mma_f16(float c[4], const uint4& a, const uint2& b) {
    asm volatile(
        "mma.sync.aligned.m16n8k16.row.col.f32.f16.f16.f32 "
        "{%0,%1,%2,%3}, {%4,%5,%6,%7}, {%8,%9}, {%0,%1,%2,%3};"
        : "+f"(c[0]), "+f"(c[1]), "+f"(c[2]), "+f"(c[3])
        : "r"(a.x), "r"(a.y), "r"(a.z), "r"(a.w), "r"(b.x), "r"(b.y));
}

// ---------------- weight prep: f32 [N][K] -> B-fragment half layout --------
__global__ void prep_w(const float* __restrict__ W, uint32_t* __restrict__ out, int K) {
    const int idx = blockIdx.x * 256 + threadIdx.x;
    const int tile = idx >> 11, j = idx & 2047;
    const int ktiles = K >> 5;
    const int ntile = tile / ktiles, ktile = tile - ntile * ktiles;
    const int reg = j & 1, lane = (j >> 1) & 31, nt = (j >> 6) & 15, kt = j >> 10;
    const int n = ntile * 128 + nt * 8 + (lane >> 2);
    const int k = ktile * 32 + kt * 16 + (lane & 3) * 2 + 8 * reg;
    out[idx] = pack_h2(W[(size_t)n * K + k], W[(size_t)n * K + k + 1]);
}

// ---------------- layernorm-ish (scalar alpha/beta, ddof=1 std) -----------
__global__ void norm_kernel(const float* __restrict__ x, __half* __restrict__ out,
                            const float* __restrict__ alpha, const float* __restrict__ beta) {
    const int row = blockIdx.x;
    const float* xr = x + (size_t)row * DM;
    __half* orow = out + (size_t)row * DM;

    float v0 = xr[threadIdx.x];
    float v1 = xr[threadIdx.x + 256];
    float v2 = xr[threadIdx.x + 512];
    float s  = v0 + v1 + v2;
    float sq = v0 * v0 + v1 * v1 + v2 * v2;

    __shared__ float red0[8], red1[8];
    __shared__ float s_mean, s_scale, s_beta;
    #pragma unroll
    for (int o = 16; o > 0; o >>= 1) {
        s  += __shfl_xor_sync(0xffffffffu, s,  o);
        sq += __shfl_xor_sync(0xffffffffu, sq, o);
    }
    const int warp = threadIdx.x >> 5, lane = threadIdx.x & 31;
    if (lane == 0) { red0[warp] = s; red1[warp] = sq; }
    __syncthreads();
    if (threadIdx.x == 0) {
        float S = 0.f, SQ = 0.f;
        #pragma unroll
        for (int i = 0; i < 8; i++) { S += red0[i]; SQ += red1[i]; }
        const float mean = S / (float)DM;
        float var = (SQ - (float)DM * mean * mean) / (float)(DM - 1);
        var = fmaxf(var, 0.f);
        s_mean  = mean;
        s_scale = alpha[0] / (sqrtf(var) + 1e-6f);
        s_beta  = beta[0];
    }
    __syncthreads();
    const float mean = s_mean, scale = s_scale, bb = s_beta;
    orow[threadIdx.x]       = __float2half_rn((v0 - mean) * scale + bb);
    orow[threadIdx.x + 256] = __float2half_rn((v1 - mean) * scale + bb);
    orow[threadIdx.x + 512] = __float2half_rn((v2 - mean) * scale + bb);
}

// =================== fp16 GEMM: half A, pre-fragged B ======================
// C = A[M,K] @ W[N,K]^T (+bias) (+res) (+relu)
// MODE 0: half out.  MODE 1: half out + relu.  MODE 2: f32 out + f32 residual.
template <int MODE>
__global__ void __launch_bounds__(256, 2)
gemm_mma(const __half* __restrict__ A, const uint32_t* __restrict__ Wf,
         const float* __restrict__ bias, const float* __restrict__ res,
         void* __restrict__ Cv, int M, int N, int K) {
    __shared__ uint32_t sm[2][4096];   // [buf][As 2048 | Bs 2048]

    const int t    = threadIdx.x;
    const int lane = t & 31;
    const int wid  = t >> 5;
    const int wy   = wid >> 2;
    const int wx   = wid & 3;
    const int bm   = blockIdx.y * 128;
    const int bn   = blockIdx.x * 128;

    const __half* Ab = A + (size_t)bm * K;
    const uint32_t* Wtile0 = Wf + (size_t)(bn >> 7) * (K >> 5) * 2048;

    float acc[4][4][4];
    #pragma unroll
    for (int i = 0; i < 4; i++)
        #pragma unroll
        for (int j = 0; j < 4; j++)
            #pragma unroll
            for (int r = 0; r < 4; r++) acc[i][j][r] = 0.f;

    auto stage_tile = [&](int ktile, int buf) {
        uint32_t* As = sm[buf];
        // A: 128 rows x 32 halves, pre-permute into fragment layout (pure u32 moves)
        #pragma unroll
        for (int p = 0; p < 4; p++) {
            const int f = t + p * 256;          // 1024 slots
            const int row = f >> 3, g = f & 7;  // g: group of 4 halves
            const uint2 pa = *(const uint2*)(Ab + (size_t)row * K + ktile * 32 + g * 4);
            const int kt = g >> 2, rhi = (g >> 1) & 1, llo = g & 1;
            const int mt = row >> 4, rr = row & 15;
            const int base = ((kt * 8 + mt) * 32 + (rr & 7) * 4 + 2 * llo) * 4
                             + (rr >> 3) + 2 * rhi;
            As[base]     = pa.x;
            As[base + 4] = pa.y;
        }
        // B: straight copy of pre-fragged tile
        uint4* Bs4 = (uint4*)(sm[buf] + 2048);
        const uint4* Wt4 = (const uint4*)(Wtile0 + (size_t)ktile * 2048);
        Bs4[t]       = Wt4[t];
        Bs4[t + 256] = Wt4[t + 256];
    };

    auto compute = [&](int buf) {
        const uint32_t* As = sm[buf];
        const uint32_t* Bs = sm[buf] + 2048;
        #pragma unroll
        for (int kt = 0; kt < 2; kt++) {
            uint4 af[4];
            uint2 bf[4];
            #pragma unroll
            for (int mt = 0; mt < 4; mt++)
                af[mt] = *(const uint4*)&As[((kt * 8 + wy * 4 + mt) * 32 + lane) * 4];
            #pragma unroll
            for (int nt = 0; nt < 4; nt++)
                bf[nt] = *(const uint2*)&Bs[((kt * 16 + wx * 4 + nt) * 32 + lane) * 2];
            #pragma unroll
            for (int mt = 0; mt < 4; mt++)
                #pragma unroll
                for (int nt = 0; nt < 4; nt++)
                    mma_f16(acc[mt][nt], af[mt], bf[nt]);
        }
    };

    const int niter = K / 32;

    stage_tile(0, 0);
    __syncthreads();

    for (int i = 0; i < niter; i++) {
        if (i + 1 < niter) stage_tile(i + 1, (i + 1) & 1);
        compute(i & 1);
        __syncthreads();
    }

    const int rbase = bm + wy * 64 + (lane >> 2);
    const int cbase = bn + wx * 32 + (lane & 3) * 2;
    #pragma unroll
    for (int mt = 0; mt < 4; mt++) {
        #pragma unroll
        for (int nt = 0; nt < 4; nt++) {
            const int c = cbase + nt * 8;
            const float b0 = bias[c], b1 = bias[c + 1];
            const int r0 = rbase + mt * 16;
            const int r1 = r0 + 8;
            float v0 = acc[mt][nt][0] + b0;
            float v1 = acc[mt][nt][1] + b1;
            float v2 = acc[mt][nt][2] + b0;
            float v3 = acc[mt][nt][3] + b1;
            if (MODE == 1) {
                v0 = fmaxf(v0, 0.f); v1 = fmaxf(v1, 0.f);
                v2 = fmaxf(v2, 0.f); v3 = fmaxf(v3, 0.f);
            }
            if (MODE == 2) {
                const float2 q0 = *(const float2*)&res[(size_t)r0 * N + c];
                const float2 q1 = *(const float2*)&res[(size_t)r1 * N + c];
                float* C = (float*)Cv;
                *(float2*)&C[(size_t)r0 * N + c] = make_float2(v0 + q0.x, v1 + q0.y);
                *(float2*)&C[(size_t)r1 * N + c] = make_float2(v2 + q1.x, v3 + q1.y);
            } else {
                __half* C = (__half*)Cv;
                *(uint32_t*)&C[(size_t)r0 * N + c] = pack_h2(v0, v1);
                *(uint32_t*)&C[(size_t)r1 * N + c] = pack_h2(v2, v3);
            }
        }
    }
}

// =================== fp16 flash attention, register-resident P =============
// CTA: 128 queries (one (b,h)); 8 warps x 16 queries; BN=64 keys/iter.
// Each warp owns its queries' FULL key strip -> softmax + P stay in registers
// (C-fragment col-pair layout == A-fragment k-pair layout).
__global__ void __launch_bounds__(256, 2)
attn_mma(const __half* __restrict__ Qh, const __half* __restrict__ Kh,
         const __half* __restrict__ Vh, const int* __restrict__ mask,
         __half* __restrict__ Oh) {
    __shared__ uint32_t Ks[2][2048];   // B-frag: kt=d/16, nt=key/8
    __shared__ uint32_t Vs[2][2048];   // B-frag: kt=key/16, nt=d/8
    __shared__ int      mki[2][64];

    const int t = threadIdx.x, lane = t & 31, wid = t >> 5;
    const int q0 = blockIdx.x * 128;
    const int h  = blockIdx.y, b = blockIdx.z;
    const size_t base = (size_t)b * S_LEN * DM + (size_t)h * DK;

    // ---- persistent Q A-fragments (16 queries per warp) ----
    const int qrow = q0 + wid * 16 + (lane >> 2);
    uint4 aq[4];
    #pragma unroll
    for (int kt = 0; kt < 4; kt++) {
        const __half* qp = Qh + base + (size_t)qrow * DM + kt * 16 + (lane & 3) * 2;
        aq[kt].x = *(const uint32_t*)qp;
        aq[kt].y = *(const uint32_t*)(qp + (size_t)8 * DM);
        aq[kt].z = *(const uint32_t*)(qp + 8);
        aq[kt].w = *(const uint32_t*)(qp + (size_t)8 * DM + 8);
    }

    float m0 = -INFINITY, m1 = -INFINITY, l0 = 0.f, l1 = 0.f;
    float o[8][4];
    #pragma unroll
    for (int i = 0; i < 8; i++)
        #pragma unroll
        for (int j = 0; j < 4; j++) o[i][j] = 0.f;

    auto stage = [&](int ks0, int buf) {
        #pragma unroll
        for (int p = 0; p < 4; p++) {
            const int f = t + p * 256;           // 1024 slots
            const int row = f >> 4, g = f & 15;  // 64 keys x 16 groups of 4 d
            const uint2 kv = *(const uint2*)(Kh + base + (size_t)(ks0 + row) * DM + g * 4);
            {
                const int nt = row >> 3, nr = row & 7;
                const int kt = g >> 2, rhi = (g >> 1) & 1, llo = g & 1;
                const int idx = ((kt * 8 + nt) * 32 + nr * 4 + 2 * llo) * 2 + rhi;
                Ks[buf][idx]     = kv.x;
                Ks[buf][idx + 2] = kv.y;
            }
            const uint2 vv = *(const uint2*)(Vh + base + (size_t)(ks0 + row) * DM + g * 4);
            {
                __half* Vhs = (__half*)Vs[buf];
                const __half* hv = (const __half*)&vv;
                const int ktv = row >> 4, regv = (row >> 3) & 1;
                const int lprt = (row >> 1) & 3, klo = row & 1;
                #pragma unroll
                for (int j = 0; j < 4; j++) {
                    const int n = g * 4 + j;
                    const int nt = n >> 3, nr = n & 7;
                    Vhs[(((ktv * 8 + nt) * 32 + nr * 4 + lprt) * 2 + regv) * 2 + klo] = hv[j];
                }
            }
        }
        if (t < 64) mki[buf][t] = mask[(size_t)b * S_LEN + ks0 + t];
    };

    stage(0, 0);
    __syncthreads();

    for (int i = 0; i < 64; i++) {
        if (i + 1 < 64) stage((i + 1) * 64, (i + 1) & 1);
        const int buf = i & 1;

        // ---- S = Q K^T (16q x 64 keys per warp) ----
        float s[8][4];
        #pragma unroll
        for (int nt = 0; nt < 8; nt++)
            #pragma unroll
            for (int r = 0; r < 4; r++) s[nt][r] = 0.f;
        #pragma unroll
        for (int kt = 0; kt < 4; kt++)
            #pragma unroll
            for (int nt = 0; nt < 8; nt++) {
                const uint2 bf = *(const uint2*)&Ks[buf][((kt * 8 + nt) * 32 + lane) * 2];
                mma_f16(s[nt], aq[kt], bf);
            }

        // ---- mask + scale + in-register row max ----
        float mx0 = -INFINITY, mx1 = -INFINITY;
        #pragma unroll
        for (int nt = 0; nt < 8; nt++) {
            const int c = nt * 8 + (lane & 3) * 2;
            const int2 mm = *(const int2*)&mki[buf][c];
            const bool ma = mm.x != 0, mb = mm.y != 0;
            s[nt][0] = ma ? s[nt][0] * 0.125f : -1e9f;
            s[nt][1] = mb ? s[nt][1] * 0.125f : -1e9f;
            s[nt][2] = ma ? s[nt][2] * 0.125f : -1e9f;
            s[nt][3] = mb ? s[nt][3] * 0.125f : -1e9f;
            mx0 = fmaxf(mx0, fmaxf(s[nt][0], s[nt][1]));
            mx1 = fmaxf(mx1, fmaxf(s[nt][2], s[nt][3]));
        }
        mx0 = fmaxf(mx0, __shfl_xor_sync(0xffffffffu, mx0, 1));
        mx0 = fmaxf(mx0, __shfl_xor_sync(0xffffffffu, mx0, 2));
        mx1 = fmaxf(mx1, __shfl_xor_sync(0xffffffffu, mx1, 1));
        mx1 = fmaxf(mx1, __shfl_xor_sync(0xffffffffu, mx1, 2));
        const float mn0 = fmaxf(m0, mx0);
        const float mn1 = fmaxf(m1, mx1);
        const float fac0 = __expf(m0 - mn0);
        const float fac1 = __expf(m1 - mn1);
        m0 = mn0; m1 = mn1;

        // ---- exp + in-register P fragments (C-frag == A-frag layout) ----
        float sum0 = 0.f, sum1 = 0.f;
        uint4 pf[4];
        #pragma unroll
        for (int k2 = 0; k2 < 4; k2++) {
            const int ne = 2 * k2, no = 2 * k2 + 1;
            const float p00 = __expf(s[ne][0] - mn0);
            const float p01 = __expf(s[ne][1] - mn0);
            const float p02 = __expf(s[ne][2] - mn1);
            const float p03 = __expf(s[ne][3] - mn1);
            const float p10 = __expf(s[no][0] - mn0);
            const float p11 = __expf(s[no][1] - mn0);
            const float p12 = __expf(s[no][2] - mn1);
            const float p13 = __expf(s[no][3] - mn1);
            sum0 += p00 + p01 + p10 + p11;
            sum1 += p02 + p03 + p12 + p13;
            pf[k2].x = pack_h2(p00, p01);
            pf[k2].y = pack_h2(p02, p03);
            pf[k2].z = pack_h2(p10, p11);
            pf[k2].w = pack_h2(p12, p13);
        }
        l0 = l0 * fac0 + sum0;
        l1 = l1 * fac1 + sum1;
        #pragma unroll
        for (int nt = 0; nt < 8; nt++) {
            o[nt][0] *= fac0; o[nt][1] *= fac0;
            o[nt][2] *= fac1; o[nt][3] *= fac1;
        }

        // ---- O += P V ----
        #pragma unroll
        for (int kt = 0; kt < 4; kt++)
            #pragma unroll
            for (int nt = 0; nt < 8; nt++) {
                const uint2 bf = *(const uint2*)&Vs[buf][((kt * 8 + nt) * 32 + lane) * 2];
                mma_f16(o[nt], pf[kt], bf);
            }
        __syncthreads();
    }

    // ---- finalize (quad-sum l, fully warp-local) ----
    l0 += __shfl_xor_sync(0xffffffffu, l0, 1);
    l0 += __shfl_xor_sync(0xffffffffu, l0, 2);
    l1 += __shfl_xor_sync(0xffffffffu, l1, 1);
    l1 += __shfl_xor_sync(0xffffffffu, l1, 2);
    const float inv0 = 1.f / l0;
    const float inv1 = 1.f / l1;

    #pragma unroll
    for (int nt = 0; nt < 8; nt++) {
        const int c = nt * 8 + (lane & 3) * 2;
        *(uint32_t*)&Oh[base + (size_t)qrow * DM + c] =
            pack_h2(o[nt][0] * inv0, o[nt][1] * inv0);
        *(uint32_t*)&Oh[base + (size_t)(qrow + 8) * DM + c] =
            pack_h2(o[nt][2] * inv1, o[nt][3] * inv1);
    }
}

// ---------------------------------------------------------------------------
extern "C" void kernel_launch(void* const* d_in, const int* in_sizes, int n_in,
                              void* d_out, int out_size) {
    const float* x      = (const float*)d_in[0];
    const int*   mask   = (const int*)  d_in[1];
    const float* wq     = (const float*)d_in[2];
    const float* bq     = (const float*)d_in[3];
    const float* wk     = (const float*)d_in[4];
    const float* bk     = (const float*)d_in[5];
    const float* wv     = (const float*)d_in[6];
    const float* bv     = (const float*)d_in[7];
    const float* wo     = (const float*)d_in[8];
    const float* bo     = (const float*)d_in[9];
    const float* w1     = (const float*)d_in[10];
    const float* b1     = (const float*)d_in[11];
    const float* w2     = (const float*)d_in[12];
    const float* b2     = (const float*)d_in[13];
    const float* alpha1 = (const float*)d_in[14];
    const float* beta1  = (const float*)d_in[15];
    const float* alpha2 = (const float*)d_in[16];
    const float* beta2  = (const float*)d_in[17];
    float* out = (float*)d_out;

    __half *h, *q, *k, *v, *ctx, *ff;
    float* x2;
    uint32_t *wqf, *wkf, *wvf, *wof, *w1f, *w2f;
    cudaGetSymbolAddress((void**)&h,   g_h);
    cudaGetSymbolAddress((void**)&q,   g_q);
    cudaGetSymbolAddress((void**)&k,   g_k);
    cudaGetSymbolAddress((void**)&v,   g_v);
    cudaGetSymbolAddress((void**)&ctx, g_ctx);
    cudaGetSymbolAddress((void**)&x2,  g_x2);
    cudaGetSymbolAddress((void**)&ff,  g_ff);
    cudaGetSymbolAddress((void**)&wqf, g_wqf);
    cudaGetSymbolAddress((void**)&wkf, g_wkf);
    cudaGetSymbolAddress((void**)&wvf, g_wvf);
    cudaGetSymbolAddress((void**)&wof, g_wof);
    cudaGetSymbolAddress((void**)&w1f, g_w1f);
    cudaGetSymbolAddress((void**)&w2f, g_w2f);

    // 0. weight prep (fragment layouts)
    prep_w<<<DM * DM / 2 / 256, 256>>>(wq, wqf, DM);
    prep_w<<<DM * DM / 2 / 256, 256>>>(wk, wkf, DM);
    prep_w<<<DM * DM / 2 / 256, 256>>>(wv, wvf, DM);
    prep_w<<<DM * DM / 2 / 256, 256>>>(wo, wof, DM);
    prep_w<<<DFF * DM / 2 / 256, 256>>>(w1, w1f, DM);
    prep_w<<<DM * DFF / 2 / 256, 256>>>(w2, w2f, DFF);

    const dim3 g_qkv(DM / 128,  NTOK / 128);   // (6, 64)
    const dim3 g_ff1(DFF / 128, NTOK / 128);   // (24, 64)
    const dim3 attn_grid(S_LEN / 128, NH, BATCH);

    // 1. h = norm1(x)  (half out)
    norm_kernel<<<NTOK, 256>>>(x, h, alpha1, beta1);
    // 2-4. q,k,v projections (half in/out)
    gemm_mma<0><<<g_qkv, 256>>>(h, wqf, bq, nullptr, q, NTOK, DM, DM);
    gemm_mma<0><<<g_qkv, 256>>>(h, wkf, bk, nullptr, k, NTOK, DM, DM);
    gemm_mma<0><<<g_qkv, 256>>>(h, wvf, bv, nullptr, v, NTOK, DM, DM);
    // 5. attention -> ctx (half)
    attn_mma<<<attn_grid, 256>>>(q, k, v, mask, ctx);
    // 6. x2 = x + ctx @ wo^T + bo  (f32 out)
    gemm_mma<2><<<g_qkv, 256>>>(ctx, wof, bo, x, x2, NTOK, DM, DM);
    // 7. h = norm2(x2) (half out)
    norm_kernel<<<NTOK, 256>>>(x2, h, alpha2, beta2);
    // 8. ff = relu(h @ w1^T + b1)  (half out)
    gemm_mma<1><<<g_ff1, 256>>>(h, w1f, b1, nullptr, ff, NTOK, DFF, DM);
    // 9. out = x2 + ff @ w2^T + b2 (f32 out)
    gemm_mma<2><<<g_qkv, 256>>>(ff, w2f, b2, x2, out, NTOK, DM, DFF);
}

// round 10
// speedup vs baseline: 4.0705x; 1.7790x over previous
#include <cuda_runtime.h>
#include <cuda_fp16.h>
#include <cstdint>
#include <math.h>

#define S_LEN 4096
#define BATCH 2
#define DM    768
#define DFF   3072
#define NH    12
#define DK    64
#define NTOK  (BATCH * S_LEN)

// ---------------- scratch (device globals: no allocation allowed) ----------
__device__ __half g_h  [NTOK * DM];
__device__ __half g_q  [NTOK * DM];
__device__ __half g_k  [NTOK * DM];
__device__ __half g_v  [NTOK * DM];
__device__ __half g_ctx[NTOK * DM];
__device__ float  g_x2 [NTOK * DM];
__device__ __half g_ff [NTOK * DFF];
// weight fragments (u32 = f16x2), layout [ntile][ktile][2048]
__device__ uint32_t g_wqf[DM * DM / 2];
__device__ uint32_t g_wkf[DM * DM / 2];
__device__ uint32_t g_wvf[DM * DM / 2];
__device__ uint32_t g_wof[DM * DM / 2];
__device__ uint32_t g_w1f[DFF * DM / 2];
__device__ uint32_t g_w2f[DM * DFF / 2];

// ---------------- helpers --------------------------------------------------
__device__ __forceinline__ uint32_t pack_h2(float lo, float hi) {
    uint32_t r; asm("cvt.rn.f16x2.f32 %0, %1, %2;" : "=r"(r) : "f"(hi), "f"(lo)); return r;
}

__device__ __forceinline__ void mma_f16(float c[4], const uint4& a, const uint2& b) {
    asm volatile(
        "mma.sync.aligned.m16n8k16.row.col.f32.f16.f16.f32 "
        "{%0,%1,%2,%3}, {%4,%5,%6,%7}, {%8,%9}, {%0,%1,%2,%3};"
        : "+f"(c[0]), "+f"(c[1]), "+f"(c[2]), "+f"(c[3])
        : "r"(a.x), "r"(a.y), "r"(a.z), "r"(a.w), "r"(b.x), "r"(b.y));
}

#define CP16(dst, src) \
    asm volatile("cp.async.ca.shared.global [%0], [%1], 16;" :: "r"(dst), "l"(src))
#define CP_COMMIT() asm volatile("cp.async.commit_group;" ::: "memory")
#define CP_WAIT(N)  asm volatile("cp.async.wait_group %0;" :: "n"(N) : "memory")

__device__ __forceinline__ void ldm_x4(uint4& r, uint32_t a) {
    asm volatile("ldmatrix.sync.aligned.m8n8.x4.shared.b16 {%0,%1,%2,%3}, [%4];"
        : "=r"(r.x), "=r"(r.y), "=r"(r.z), "=r"(r.w) : "r"(a));
}
__device__ __forceinline__ void ldm_x4t(uint4& r, uint32_t a) {
    asm volatile("ldmatrix.sync.aligned.m8n8.x4.trans.shared.b16 {%0,%1,%2,%3}, [%4];"
        : "=r"(r.x), "=r"(r.y), "=r"(r.z), "=r"(r.w) : "r"(a));
}

// ---------------- weight prep: f32 [N][K] -> B-fragment half layout --------
__global__ void prep_w(const float* __restrict__ W, uint32_t* __restrict__ out, int K) {
    const int idx = blockIdx.x * 256 + threadIdx.x;
    const int tile = idx >> 11, j = idx & 2047;
    const int ktiles = K >> 5;
    const int ntile = tile / ktiles, ktile = tile - ntile * ktiles;
    const int reg = j & 1, lane = (j >> 1) & 31, nt = (j >> 6) & 15, kt = j >> 10;
    const int n = ntile * 128 + nt * 8 + (lane >> 2);
    const int k = ktile * 32 + kt * 16 + (lane & 3) * 2 + 8 * reg;
    out[idx] = pack_h2(W[(size_t)n * K + k], W[(size_t)n * K + k + 1]);
}

// ---------------- layernorm-ish (scalar alpha/beta, ddof=1 std) -----------
__global__ void norm_kernel(const float* __restrict__ x, __half* __restrict__ out,
                            const float* __restrict__ alpha, const float* __restrict__ beta) {
    const int row = blockIdx.x;
    const float* xr = x + (size_t)row * DM;
    __half* orow = out + (size_t)row * DM;

    float v0 = xr[threadIdx.x];
    float v1 = xr[threadIdx.x + 256];
    float v2 = xr[threadIdx.x + 512];
    float s  = v0 + v1 + v2;
    float sq = v0 * v0 + v1 * v1 + v2 * v2;

    __shared__ float red0[8], red1[8];
    __shared__ float s_mean, s_scale, s_beta;
    #pragma unroll
    for (int o = 16; o > 0; o >>= 1) {
        s  += __shfl_xor_sync(0xffffffffu, s,  o);
        sq += __shfl_xor_sync(0xffffffffu, sq, o);
    }
    const int warp = threadIdx.x >> 5, lane = threadIdx.x & 31;
    if (lane == 0) { red0[warp] = s; red1[warp] = sq; }
    __syncthreads();
    if (threadIdx.x == 0) {
        float S = 0.f, SQ = 0.f;
        #pragma unroll
        for (int i = 0; i < 8; i++) { S += red0[i]; SQ += red1[i]; }
        const float mean = S / (float)DM;
        float var = (SQ - (float)DM * mean * mean) / (float)(DM - 1);
        var = fmaxf(var, 0.f);
        s_mean  = mean;
        s_scale = alpha[0] / (sqrtf(var) + 1e-6f);
        s_beta  = beta[0];
    }
    __syncthreads();
    const float mean = s_mean, scale = s_scale, bb = s_beta;
    orow[threadIdx.x]       = __float2half_rn((v0 - mean) * scale + bb);
    orow[threadIdx.x + 256] = __float2half_rn((v1 - mean) * scale + bb);
    orow[threadIdx.x + 512] = __float2half_rn((v2 - mean) * scale + bb);
}

// =================== fp16 GEMM: cp.async + ldmatrix A, pre-fragged B =======
// C = A[M,K] @ W[N,K]^T (+bias).  MODE 0: half out. 1: half+relu. 2: f32+res.
// 3-stage ring, distance-1 prefetch, 1 sync/iter.
// A tile: 128 rows x 32 halves row-major, 80B row stride (bank-conflict-free).
#define G_STG   18432                     // 10240 (A) + 8192 (B)
#define G_DSMEM (3 * G_STG)

template <int MODE>
__global__ void __launch_bounds__(256, 2)
gemm_mma(const __half* __restrict__ A, const uint32_t* __restrict__ Wf,
         const float* __restrict__ bias, const float* __restrict__ res,
         void* __restrict__ Cv, int M, int N, int K) {
    extern __shared__ char smc[];
    const uint32_t sb = (uint32_t)__cvta_generic_to_shared(smc);

    const int t    = threadIdx.x;
    const int lane = t & 31;
    const int wid  = t >> 5;
    const int wy   = wid >> 2;
    const int wx   = wid & 3;
    const int bm   = blockIdx.y * 128;
    const int bn   = blockIdx.x * 128;

    const __half* Ab = A + (size_t)bm * K;
    const uint32_t* Wtile0 = Wf + (size_t)(bn >> 7) * (K >> 5) * 2048;

    float acc[4][4][4];
    #pragma unroll
    for (int i = 0; i < 4; i++)
        #pragma unroll
        for (int j = 0; j < 4; j++)
            #pragma unroll
            for (int r = 0; r < 4; r++) acc[i][j][r] = 0.f;

    const int arowp = t >> 2, achp = t & 3;     // A staging coords (2 rows/thread)

    auto stage = [&](int ktile, int s) {
        const uint32_t ab = sb + s * G_STG;
        #pragma unroll
        for (int p = 0; p < 2; p++) {
            const int row = arowp + p * 64;
            CP16(ab + row * 80 + achp * 16,
                 (const char*)(Ab + (size_t)row * K + ktile * 32) + achp * 16);
        }
        const uint32_t bb = ab + 10240;
        const char* wsrc = (const char*)(Wtile0 + (size_t)ktile * 2048);
        CP16(bb + t * 16,        wsrc + t * 16);
        CP16(bb + (t + 256) * 16, wsrc + (t + 256) * 16);
    };

    const int army = ((lane >> 3) & 1) * 8 + (lane & 7);   // ldmatrix A row part
    const int acol = ((lane >> 4) & 1) * 8;                // ldmatrix A col part

    auto compute = [&](int s) {
        const uint32_t ab = sb + s * G_STG;
        const uint32_t* Bs = (const uint32_t*)(smc + s * G_STG + 10240);
        #pragma unroll
        for (int kt = 0; kt < 2; kt++) {
            uint4 af[4];
            #pragma unroll
            for (int mt = 0; mt < 4; mt++)
                ldm_x4(af[mt], ab + (uint32_t)((wy * 64 + mt * 16 + army) * 80
                                               + (kt * 16 + acol) * 2));
            uint2 bf[4];
            #pragma unroll
            for (int nt = 0; nt < 4; nt++)
                bf[nt] = *(const uint2*)&Bs[((kt * 16 + wx * 4 + nt) * 32 + lane) * 2];
            #pragma unroll
            for (int mt = 0; mt < 4; mt++)
                #pragma unroll
                for (int nt = 0; nt < 4; nt++)
                    mma_f16(acc[mt][nt], af[mt], bf[nt]);
        }
    };

    const int niter = K / 32;

    stage(0, 0);
    CP_COMMIT();
    for (int i = 0; i < niter; i++) {
        if (i + 1 < niter) {
            stage(i + 1, (i + 1) % 3);
            CP_COMMIT();
            CP_WAIT(1);
        } else {
            CP_WAIT(0);
        }
        __syncthreads();
        compute(i % 3);
    }

    const int rbase = bm + wy * 64 + (lane >> 2);
    const int cbase = bn + wx * 32 + (lane & 3) * 2;
    #pragma unroll
    for (int mt = 0; mt < 4; mt++) {
        #pragma unroll
        for (int nt = 0; nt < 4; nt++) {
            const int c = cbase + nt * 8;
            const float b0 = bias[c], b1 = bias[c + 1];
            const int r0 = rbase + mt * 16;
            const int r1 = r0 + 8;
            float v0 = acc[mt][nt][0] + b0;
            float v1 = acc[mt][nt][1] + b1;
            float v2 = acc[mt][nt][2] + b0;
            float v3 = acc[mt][nt][3] + b1;
            if (MODE == 1) {
                v0 = fmaxf(v0, 0.f); v1 = fmaxf(v1, 0.f);
                v2 = fmaxf(v2, 0.f); v3 = fmaxf(v3, 0.f);
            }
            if (MODE == 2) {
                const float2 q0 = *(const float2*)&res[(size_t)r0 * N + c];
                const float2 q1 = *(const float2*)&res[(size_t)r1 * N + c];
                float* C = (float*)Cv;
                *(float2*)&C[(size_t)r0 * N + c] = make_float2(v0 + q0.x, v1 + q0.y);
                *(float2*)&C[(size_t)r1 * N + c] = make_float2(v2 + q1.x, v3 + q1.y);
            } else {
                __half* C = (__half*)Cv;
                *(uint32_t*)&C[(size_t)r0 * N + c] = pack_h2(v0, v1);
                *(uint32_t*)&C[(size_t)r1 * N + c] = pack_h2(v2, v3);
            }
        }
    }
}

// =================== fp16 flash attention: cp.async + ldmatrix =============
// CTA: 128 queries (one (b,h)); 8 warps x 16 queries; BN=64 keys/iter.
// K,V row-major in smem (144B row stride), frags via ldmatrix / ldmatrix.trans.
// 3-stage ring, 1 sync/iter, register-resident P.
#define A_STG   18688                 // K 9216 + V 9216 + mask 256
#define A_DSMEM (3 * A_STG)

__global__ void __launch_bounds__(256, 2)
attn_mma(const __half* __restrict__ Qh, const __half* __restrict__ Kh,
         const __half* __restrict__ Vh, const int* __restrict__ mask,
         __half* __restrict__ Oh) {
    extern __shared__ char smc[];
    const uint32_t sb = (uint32_t)__cvta_generic_to_shared(smc);

    const int t = threadIdx.x, lane = t & 31, wid = t >> 5;
    const int q0 = blockIdx.x * 128;
    const int h  = blockIdx.y, b = blockIdx.z;
    const size_t base = (size_t)b * S_LEN * DM + (size_t)h * DK;

    // ---- persistent Q A-fragments (16 queries per warp) ----
    const int qrow = q0 + wid * 16 + (lane >> 2);
    uint4 aq[4];
    #pragma unroll
    for (int kt = 0; kt < 4; kt++) {
        const __half* qp = Qh + base + (size_t)qrow * DM + kt * 16 + (lane & 3) * 2;
        aq[kt].x = *(const uint32_t*)qp;
        aq[kt].y = *(const uint32_t*)(qp + (size_t)8 * DM);
        aq[kt].z = *(const uint32_t*)(qp + 8);
        aq[kt].w = *(const uint32_t*)(qp + (size_t)8 * DM + 8);
    }

    float m0 = -INFINITY, m1 = -INFINITY, l0 = 0.f, l1 = 0.f;
    float o[8][4];
    #pragma unroll
    for (int i = 0; i < 8; i++)
        #pragma unroll
        for (int j = 0; j < 4; j++) o[i][j] = 0.f;

    const int srow = t >> 3, sch = t & 7;   // staging: 512 16B chunks per matrix

    auto stage = [&](int ks0, int s) {
        const uint32_t kb = sb + s * A_STG;
        #pragma unroll
        for (int p = 0; p < 2; p++) {
            const int row = srow + p * 32;
            const char* ksrc = (const char*)(Kh + base + (size_t)(ks0 + row) * DM) + sch * 16;
            const char* vsrc = (const char*)(Vh + base + (size_t)(ks0 + row) * DM) + sch * 16;
            CP16(kb + row * 144 + sch * 16, ksrc);
            CP16(kb + 9216 + row * 144 + sch * 16, vsrc);
        }
        if (t < 16)
            CP16(kb + 18432 + t * 16, (const char*)(mask + (size_t)b * S_LEN + ks0) + t * 16);
    };

    // ldmatrix lane-address parts
    const int krow = ((lane >> 4) & 1) * 8 + (lane & 7);   // K (non-trans)
    const int kcol = ((lane >> 3) & 1) * 8;
    const int vrow = ((lane >> 3) & 1) * 8 + (lane & 7);   // V (trans)
    const int vcol = ((lane >> 4) & 1) * 8;

    stage(0, 0);
    CP_COMMIT();

    for (int i = 0; i < 64; i++) {
        if (i + 1 < 64) {
            stage((i + 1) * 64, (i + 1) % 3);
            CP_COMMIT();
            CP_WAIT(1);
        } else {
            CP_WAIT(0);
        }
        __syncthreads();
        const int s = i % 3;
        const uint32_t kb = sb + s * A_STG;
        const uint32_t vb = kb + 9216;
        const int* mk = (const int*)(smc + s * A_STG + 18432);

        // ---- S = Q K^T ----
        float sc[8][4];
        #pragma unroll
        for (int nt = 0; nt < 8; nt++)
            #pragma unroll
            for (int r = 0; r < 4; r++) sc[nt][r] = 0.f;
        #pragma unroll
        for (int kt = 0; kt < 4; kt++) {
            uint2 bf[8];
            #pragma unroll
            for (int kg = 0; kg < 4; kg++) {
                uint4 r4;
                ldm_x4(r4, kb + (uint32_t)((kg * 16 + krow) * 144 + (kt * 16 + kcol) * 2));
                bf[2 * kg]     = make_uint2(r4.x, r4.y);
                bf[2 * kg + 1] = make_uint2(r4.z, r4.w);
            }
            #pragma unroll
            for (int nt = 0; nt < 8; nt++)
                mma_f16(sc[nt], aq[kt], bf[nt]);
        }

        // ---- mask + scale + in-register row max ----
        float mx0 = -INFINITY, mx1 = -INFINITY;
        #pragma unroll
        for (int nt = 0; nt < 8; nt++) {
            const int c = nt * 8 + (lane & 3) * 2;
            const int2 mm = *(const int2*)&mk[c];
            const bool ma = mm.x != 0, mb = mm.y != 0;
            sc[nt][0] = ma ? sc[nt][0] * 0.125f : -1e9f;
            sc[nt][1] = mb ? sc[nt][1] * 0.125f : -1e9f;
            sc[nt][2] = ma ? sc[nt][2] * 0.125f : -1e9f;
            sc[nt][3] = mb ? sc[nt][3] * 0.125f : -1e9f;
            mx0 = fmaxf(mx0, fmaxf(sc[nt][0], sc[nt][1]));
            mx1 = fmaxf(mx1, fmaxf(sc[nt][2], sc[nt][3]));
        }
        mx0 = fmaxf(mx0, __shfl_xor_sync(0xffffffffu, mx0, 1));
        mx0 = fmaxf(mx0, __shfl_xor_sync(0xffffffffu, mx0, 2));
        mx1 = fmaxf(mx1, __shfl_xor_sync(0xffffffffu, mx1, 1));
        mx1 = fmaxf(mx1, __shfl_xor_sync(0xffffffffu, mx1, 2));
        const float mn0 = fmaxf(m0, mx0);
        const float mn1 = fmaxf(m1, mx1);
        const float fac0 = __expf(m0 - mn0);
        const float fac1 = __expf(m1 - mn1);
        m0 = mn0; m1 = mn1;

        // ---- exp + in-register P fragments ----
        float sum0 = 0.f, sum1 = 0.f;
        uint4 pf[4];
        #pragma unroll
        for (int k2 = 0; k2 < 4; k2++) {
            const int ne = 2 * k2, no = 2 * k2 + 1;
            const float p00 = __expf(sc[ne][0] - mn0);
            const float p01 = __expf(sc[ne][1] - mn0);
            const float p02 = __expf(sc[ne][2] - mn1);
            const float p03 = __expf(sc[ne][3] - mn1);
            const float p10 = __expf(sc[no][0] - mn0);
            const float p11 = __expf(sc[no][1] - mn0);
            const float p12 = __expf(sc[no][2] - mn1);
            const float p13 = __expf(sc[no][3] - mn1);
            sum0 += p00 + p01 + p10 + p11;
            sum1 += p02 + p03 + p12 + p13;
            pf[k2].x = pack_h2(p00, p01);
            pf[k2].y = pack_h2(p02, p03);
            pf[k2].z = pack_h2(p10, p11);
            pf[k2].w = pack_h2(p12, p13);
        }
        l0 = l0 * fac0 + sum0;
        l1 = l1 * fac1 + sum1;
        #pragma unroll
        for (int nt = 0; nt < 8; nt++) {
            o[nt][0] *= fac0; o[nt][1] *= fac0;
            o[nt][2] *= fac1; o[nt][3] *= fac1;
        }

        // ---- O += P V  (V frags via ldmatrix.trans) ----
        #pragma unroll
        for (int kt2 = 0; kt2 < 4; kt2++) {
            #pragma unroll
            for (int dp = 0; dp < 4; dp++) {
                uint4 r4;
                ldm_x4t(r4, vb + (uint32_t)((kt2 * 16 + vrow) * 144 + (dp * 16 + vcol) * 2));
                mma_f16(o[2 * dp],     pf[kt2], make_uint2(r4.x, r4.y));
                mma_f16(o[2 * dp + 1], pf[kt2], make_uint2(r4.z, r4.w));
            }
        }
    }

    // ---- finalize (quad-sum l, fully warp-local) ----
    l0 += __shfl_xor_sync(0xffffffffu, l0, 1);
    l0 += __shfl_xor_sync(0xffffffffu, l0, 2);
    l1 += __shfl_xor_sync(0xffffffffu, l1, 1);
    l1 += __shfl_xor_sync(0xffffffffu, l1, 2);
    const float inv0 = 1.f / l0;
    const float inv1 = 1.f / l1;

    #pragma unroll
    for (int nt = 0; nt < 8; nt++) {
        const int c = nt * 8 + (lane & 3) * 2;
        *(uint32_t*)&Oh[base + (size_t)qrow * DM + c] =
            pack_h2(o[nt][0] * inv0, o[nt][1] * inv0);
        *(uint32_t*)&Oh[base + (size_t)(qrow + 8) * DM + c] =
            pack_h2(o[nt][2] * inv1, o[nt][3] * inv1);
    }
}

// ---------------------------------------------------------------------------
extern "C" void kernel_launch(void* const* d_in, const int* in_sizes, int n_in,
                              void* d_out, int out_size) {
    const float* x      = (const float*)d_in[0];
    const int*   mask   = (const int*)  d_in[1];
    const float* wq     = (const float*)d_in[2];
    const float* bq     = (const float*)d_in[3];
    const float* wk     = (const float*)d_in[4];
    const float* bk     = (const float*)d_in[5];
    const float* wv     = (const float*)d_in[6];
    const float* bv     = (const float*)d_in[7];
    const float* wo     = (const float*)d_in[8];
    const float* bo     = (const float*)d_in[9];
    const float* w1     = (const float*)d_in[10];
    const float* b1     = (const float*)d_in[11];
    const float* w2     = (const float*)d_in[12];
    const float* b2     = (const float*)d_in[13];
    const float* alpha1 = (const float*)d_in[14];
    const float* beta1  = (const float*)d_in[15];
    const float* alpha2 = (const float*)d_in[16];
    const float* beta2  = (const float*)d_in[17];
    float* out = (float*)d_out;

    __half *h, *q, *k, *v, *ctx, *ff;
    float* x2;
    uint32_t *wqf, *wkf, *wvf, *wof, *w1f, *w2f;
    cudaGetSymbolAddress((void**)&h,   g_h);
    cudaGetSymbolAddress((void**)&q,   g_q);
    cudaGetSymbolAddress((void**)&k,   g_k);
    cudaGetSymbolAddress((void**)&v,   g_v);
    cudaGetSymbolAddress((void**)&ctx, g_ctx);
    cudaGetSymbolAddress((void**)&x2,  g_x2);
    cudaGetSymbolAddress((void**)&ff,  g_ff);
    cudaGetSymbolAddress((void**)&wqf, g_wqf);
    cudaGetSymbolAddress((void**)&wkf, g_wkf);
    cudaGetSymbolAddress((void**)&wvf, g_wvf);
    cudaGetSymbolAddress((void**)&wof, g_wof);
    cudaGetSymbolAddress((void**)&w1f, g_w1f);
    cudaGetSymbolAddress((void**)&w2f, g_w2f);

    cudaFuncSetAttribute(gemm_mma<0>, cudaFuncAttributeMaxDynamicSharedMemorySize, G_DSMEM);
    cudaFuncSetAttribute(gemm_mma<1>, cudaFuncAttributeMaxDynamicSharedMemorySize, G_DSMEM);
    cudaFuncSetAttribute(gemm_mma<2>, cudaFuncAttributeMaxDynamicSharedMemorySize, G_DSMEM);
    cudaFuncSetAttribute(attn_mma,    cudaFuncAttributeMaxDynamicSharedMemorySize, A_DSMEM);

    // 0. weight prep (fragment layouts)
    prep_w<<<DM * DM / 2 / 256, 256>>>(wq, wqf, DM);
    prep_w<<<DM * DM / 2 / 256, 256>>>(wk, wkf, DM);
    prep_w<<<DM * DM / 2 / 256, 256>>>(wv, wvf, DM);
    prep_w<<<DM * DM / 2 / 256, 256>>>(wo, wof, DM);
    prep_w<<<DFF * DM / 2 / 256, 256>>>(w1, w1f, DM);
    prep_w<<<DM * DFF / 2 / 256, 256>>>(w2, w2f, DFF);

    const dim3 g_qkv(DM / 128,  NTOK / 128);   // (6, 64)
    const dim3 g_ff1(DFF / 128, NTOK / 128);   // (24, 64)
    const dim3 attn_grid(S_LEN / 128, NH, BATCH);

    // 1. h = norm1(x)  (half out)
    norm_kernel<<<NTOK, 256>>>(x, h, alpha1, beta1);
    // 2-4. q,k,v projections
    gemm_mma<0><<<g_qkv, 256, G_DSMEM>>>(h, wqf, bq, nullptr, q, NTOK, DM, DM);
    gemm_mma<0><<<g_qkv, 256, G_DSMEM>>>(h, wkf, bk, nullptr, k, NTOK, DM, DM);
    gemm_mma<0><<<g_qkv, 256, G_DSMEM>>>(h, wvf, bv, nullptr, v, NTOK, DM, DM);
    // 5. attention -> ctx
    attn_mma<<<attn_grid, 256, A_DSMEM>>>(q, k, v, mask, ctx);
    // 6. x2 = x + ctx @ wo^T + bo  (f32 out)
    gemm_mma<2><<<g_qkv, 256, G_DSMEM>>>(ctx, wof, bo, x, x2, NTOK, DM, DM);
    // 7. h = norm2(x2) (half out)
    norm_kernel<<<NTOK, 256>>>(x2, h, alpha2, beta2);
    // 8. ff = relu(h @ w1^T + b1)  (half out)
    gemm_mma<1><<<g_ff1, 256, G_DSMEM>>>(h, w1f, b1, nullptr, ff, NTOK, DFF, DM);
    // 9. out = x2 + ff @ w2^T + b2 (f32 out)
    gemm_mma<2><<<g_qkv, 256, G_DSMEM>>>(ff, w2f, b2, x2, out, NTOK, DM, DFF);
}